// round 1
// baseline (speedup 1.0000x reference)
#include <cuda_runtime.h>
#include <math.h>

// Problem constants
#define Bc 64
#define Tc 512
#define Ic 512
#define Hc 512
#define Oc 512

// Scratch (static device arrays: allocation-free per harness rules)
__device__ float g_Pr[(long)Bc * Tc * Hc];   // pre-act r  -> later holds zr
__device__ float g_Pz[(long)Bc * Tc * Hc];   // pre-act z  -> later holds z
__device__ float g_Ph[(long)Bc * Tc * Hc];   // pre-act h (x part)
__device__ float g_hn[(long)Bc * Tc * Hc];   // h_new
__device__ float g_hpr[Bc * Hc];             // h0 @ Wr_h + br
__device__ float g_hpz[Bc * Hc];             // h0 @ Wz_h + bz

__device__ __forceinline__ float sigmoidf_(float x) {
    return 1.0f / (1.0f + expf(-x));
}

// ---------------------------------------------------------------------------
// h-part: hpr[b][n] = br[n] + sum_k h0[b][k] * Wr_h[k][n]   (64x512, tiny)
// ---------------------------------------------------------------------------
__global__ void hpart_kernel(const float* __restrict__ h0,
                             const float* __restrict__ Wr_h,
                             const float* __restrict__ br,
                             const float* __restrict__ Wz_h,
                             const float* __restrict__ bz) {
    int b = blockIdx.x;
    int n = threadIdx.x;
    float ar = br[n];
    float az = bz[n];
    const float* h0b = h0 + b * Hc;
    for (int k = 0; k < Hc; k++) {
        float h = h0b[k];
        ar = fmaf(h, Wr_h[k * Hc + n], ar);
        az = fmaf(h, Wz_h[k * Hc + n], az);
    }
    g_hpr[b * Hc + n] = ar;
    g_hpz[b * Hc + n] = az;
}

// ---------------------------------------------------------------------------
// Tiled fp32 GEMM: C[M,512] = A[M,512] @ B[512,512]  (lda = ldb = ldc = 512)
// BM=128, BN=128, BK=8, 256 threads, 8x8 register tile per thread.
//
// MODE 0: A = x (row map through (b,t)), C = g_Pr/g_Pz/g_Ph per sel. Raw store.
// MODE 1: A = g_Pr (zr), C = g_hn.
//         epi: h1 = tanh(g_Ph + acc + bh[n]); hn = (1-z)*h0[b][n] + z*h1
// MODE 2: A = g_hn, C = out. epi: sigmoid(acc + bo[n])
// ---------------------------------------------------------------------------
template <int MODE>
__global__ __launch_bounds__(256)
void gemm_k(const float* __restrict__ A,      // MODE 0: x base
            const float* __restrict__ Bw,     // weight base (ld=512)
            float* __restrict__ Cout,         // MODE 2: d_out
            const float* __restrict__ bias,   // MODE 1: bh, MODE 2: bo
            const float* __restrict__ h0,     // MODE 1
            int sel, int Nt, int Tfull)
{
    __shared__ float As[8][128];
    __shared__ float Bs[8][128];

    const int tid = threadIdx.x;
    const int m0 = blockIdx.y * 128;
    const int n0 = blockIdx.x * 128;

    // Select A / C
    const float* Ap;
    float* Cp;
    if (MODE == 0) {
        Ap = A;
        Cp = (sel == 0) ? g_Pr : (sel == 1) ? g_Pz : g_Ph;
    } else if (MODE == 1) {
        Ap = g_Pr;   // zr
        Cp = g_hn;
    } else {
        Ap = g_hn;
        Cp = Cout;
    }

    // A loader: 128 rows x 8 cols as float4; thread -> (row = tid/2, kcol = (tid&1)*4)
    const int lrow = tid >> 1;
    const int lk   = (tid & 1) * 4;
    int gm = m0 + lrow;
    long arow;
    if (MODE == 0) {
        int b = gm / Nt;
        int t = gm - b * Nt;
        arow = (long)b * Tfull + t;   // x has Tfull rows per batch
    } else {
        arow = gm;
    }
    const float* Aptr = Ap + arow * 512 + lk;

    // B loader: 8 rows x 128 cols as float4; thread -> (row = tid/32, col = (tid&31)*4)
    const int brow = tid >> 5;
    const int bcol = (tid & 31) * 4;
    const float* Bptr = Bw + (long)brow * 512 + n0 + bcol;

    const int ty = tid >> 4;   // 0..15
    const int tx = tid & 15;   // 0..15

    float acc[8][8];
#pragma unroll
    for (int i = 0; i < 8; i++)
#pragma unroll
        for (int j = 0; j < 8; j++) acc[i][j] = 0.0f;

    for (int kt = 0; kt < 512 / 8; kt++) {
        float4 av = *(const float4*)(Aptr + kt * 8);
        float4 bv = *(const float4*)(Bptr + (long)kt * 8 * 512);

        __syncthreads();   // previous iter's reads done before overwrite
        As[lk + 0][lrow] = av.x;
        As[lk + 1][lrow] = av.y;
        As[lk + 2][lrow] = av.z;
        As[lk + 3][lrow] = av.w;
        *(float4*)&Bs[brow][bcol] = bv;
        __syncthreads();

#pragma unroll
        for (int k = 0; k < 8; k++) {
            float a[8], bb[8];
            *(float4*)&a[0]  = *(const float4*)&As[k][ty * 8];
            *(float4*)&a[4]  = *(const float4*)&As[k][ty * 8 + 4];
            *(float4*)&bb[0] = *(const float4*)&Bs[k][tx * 8];
            *(float4*)&bb[4] = *(const float4*)&Bs[k][tx * 8 + 4];
#pragma unroll
            for (int i = 0; i < 8; i++)
#pragma unroll
                for (int j = 0; j < 8; j++)
                    acc[i][j] = fmaf(a[i], bb[j], acc[i][j]);
        }
    }

    // Epilogue
#pragma unroll
    for (int i = 0; i < 8; i++) {
        int gmi = m0 + ty * 8 + i;
#pragma unroll
        for (int j = 0; j < 8; j++) {
            int gn = n0 + tx * 8 + j;
            long idx = (long)gmi * 512 + gn;
            float v = acc[i][j];
            if (MODE == 0) {
                Cp[idx] = v;
            } else if (MODE == 1) {
                float z  = g_Pz[idx];                       // holds z
                float h1 = tanhf(g_Ph[idx] + v + bias[gn]);
                int b = gmi / Nt;
                Cp[idx] = (1.0f - z) * h0[b * 512 + gn] + z * h1;
            } else {
                Cp[idx] = sigmoidf_(v + bias[gn]);
            }
        }
    }
}

// ---------------------------------------------------------------------------
// Elementwise gates after stage 1: r, z, zr (in-place into g_Pr/g_Pz)
// ---------------------------------------------------------------------------
__global__ void ew_rz_kernel(int Nt) {
    long i = (long)blockIdx.x * blockDim.x + threadIdx.x;
    int m = (int)(i >> 9);
    int n = (int)(i & 511);
    int b = m / Nt;
    float r = sigmoidf_(g_Pr[i] + g_hpr[b * 512 + n]);
    float z = sigmoidf_(g_Pz[i] + g_hpz[b * 512 + n]);
    g_Pr[i] = z * r;   // zr
    g_Pz[i] = z;       // z
}

// ---------------------------------------------------------------------------
// Copy h0 into tail of output (tuple (out, h0))
// ---------------------------------------------------------------------------
__global__ void copy_h0_kernel(const float* __restrict__ h0, float* __restrict__ dst) {
    int i = blockIdx.x * blockDim.x + threadIdx.x;
    dst[i] = h0[i];
}

// ---------------------------------------------------------------------------
extern "C" void kernel_launch(void* const* d_in, const int* in_sizes, int n_in,
                              void* d_out, int out_size) {
    const float* x  = (const float*)d_in[0];
    const float* h0 = (const float*)d_in[1];
    const float* Wr = (const float*)d_in[2];
    const float* br = (const float*)d_in[3];
    const float* Wz = (const float*)d_in[4];
    const float* bz = (const float*)d_in[5];
    const float* Wh = (const float*)d_in[6];
    const float* bh = (const float*)d_in[7];
    const float* Wo = (const float*)d_in[8];
    const float* bo = (const float*)d_in[9];
    float* out = (float*)d_out;

    // Derive N (timesteps) and tuple layout from out_size; x's T from its size.
    long os = out_size;
    int Tfull = in_sizes[0] / (Bc * Ic);
    int Nt;
    bool with_h0;
    if (os > (long)Bc * Hc && ((os - (long)Bc * Hc) % ((long)Bc * Oc)) == 0) {
        Nt = (int)((os - (long)Bc * Hc) / ((long)Bc * Oc));
        with_h0 = true;
    } else {
        Nt = (int)(os / ((long)Bc * Oc));
        with_h0 = false;
    }
    int M = Bc * Nt;   // 32768 for Nt=512

    // Stage 0: h-parts (uses Wr_h = Wr + I*H rows)
    hpart_kernel<<<Bc, Hc>>>(h0, Wr + (long)Ic * Hc, br, Wz + (long)Ic * Hc, bz);

    // Stage 1: P{r,z,h} = x @ W{r,z,h}_x  (x-parts are the first I rows of each W)
    dim3 grid(Oc / 128, M / 128);
    gemm_k<0><<<grid, 256>>>(x, Wr, nullptr, nullptr, nullptr, 0, Nt, Tfull);
    gemm_k<0><<<grid, 256>>>(x, Wz, nullptr, nullptr, nullptr, 1, Nt, Tfull);
    gemm_k<0><<<grid, 256>>>(x, Wh, nullptr, nullptr, nullptr, 2, Nt, Tfull);

    // Elementwise: r, z, zr
    long total = (long)M * Hc;
    ew_rz_kernel<<<(unsigned)(total / 256), 256>>>(Nt);

    // Stage 2: Q = zr @ Wh_h ; fused h_new epilogue
    gemm_k<1><<<grid, 256>>>(nullptr, Wh + (long)Ic * Hc, nullptr, bh, h0, 0, Nt, Tfull);

    // Stage 3: out = sigmoid(h_new @ Wo + bo)
    gemm_k<2><<<grid, 256>>>(nullptr, Wo, out, bo, nullptr, 0, Nt, Tfull);

    // Tuple tail: h0 passthrough
    if (with_h0) {
        copy_h0_kernel<<<(Bc * Hc) / 256, 256>>>(h0, out + (long)M * Oc);
    }
}

// round 3
// speedup vs baseline: 2.5991x; 2.5991x over previous
#include <cuda_runtime.h>
#include <cstdint>
#include <math.h>

#define Bc 64
#define Tc 512
#define Ic 512
#define Hc 512
#define Oc 512

// Scratch
__device__ float g_Pr[(long)Bc * Tc * Hc];   // pre-act r -> later zr
__device__ float g_Pz[(long)Bc * Tc * Hc];   // pre-act z -> later z
__device__ float g_Ph[(long)Bc * Tc * Hc];   // pre-act h (x part)
__device__ float g_hn[(long)Bc * Tc * Hc];   // h_new
__device__ float g_hpr[Bc * Hc];
__device__ float g_hpz[Bc * Hc];
__device__ float g_WT[5l * 512 * 512];       // transposed weights [N][K]

__device__ __forceinline__ float sigmoidf_(float x) { return 1.0f / (1.0f + expf(-x)); }

__device__ __forceinline__ uint32_t f2tf(float f) {
    uint32_t u;
    asm("cvt.rna.tf32.f32 %0, %1;" : "=r"(u) : "f"(f));
    return u;
}

__device__ __forceinline__ void mma_tf32(float* c, const uint32_t* a, const uint32_t* b) {
    asm volatile(
        "mma.sync.aligned.m16n8k8.row.col.f32.tf32.tf32.f32 "
        "{%0,%1,%2,%3}, {%4,%5,%6,%7}, {%8,%9}, {%0,%1,%2,%3};"
        : "+f"(c[0]), "+f"(c[1]), "+f"(c[2]), "+f"(c[3])
        : "r"(a[0]), "r"(a[1]), "r"(a[2]), "r"(a[3]), "r"(b[0]), "r"(b[1]));
}

// ---------------------------------------------------------------------------
// tf32 mma.sync GEMM: C[M,512] tiles 128x128, BK=16, 256 thr, 8 warps (4Mx2N)
// warp tile 32x64: 2 m16 x 8 n8, 2 k8 steps per BK.
// SMEM: As[m][k] pitch 20 floats, Bs[n][k] pitch 20 (B given as [N][K] = W^T).
// MODE 0: A=x (b,t map), weight sel = blockIdx.x>>2, raw store to g_P*
// MODE 1: A=g_Pr (zr), B=Wh_h^T, epi: h_new
// MODE 2: A=g_hn, B=Wo^T, epi: sigmoid
// ---------------------------------------------------------------------------
#define PITCH 20

template <int MODE>
__global__ __launch_bounds__(256)
void tgemm(const float* __restrict__ Ain, float* __restrict__ Cout,
           const float* __restrict__ bias, const float* __restrict__ h0,
           int Nt, int Tfull)
{
    __shared__ float sm[2][2][128 * PITCH];   // [buf][A=0/B=1]

    const int tid = threadIdx.x;
    const int wid = tid >> 5;
    const int lid = tid & 31;
    const int g = lid >> 2;       // groupID
    const int t = lid & 3;        // thread in group
    const int warpM = wid & 3;    // 0..3 -> 32-row slabs
    const int warpN = wid >> 2;   // 0..1 -> 64-col slabs

    const int m0 = blockIdx.y * 128;
    int nb, sel;
    if (MODE == 0) { nb = blockIdx.x & 3; sel = blockIdx.x >> 2; }
    else           { nb = blockIdx.x;     sel = 0; }
    const int n0 = nb * 128;

    const float* Ap;
    const float* Bp;
    float* Cp;
    if (MODE == 0) {
        Ap = Ain;
        Bp = g_WT + (long)sel * 512 * 512;
        Cp = (sel == 0) ? g_Pr : (sel == 1) ? g_Pz : g_Ph;
    } else if (MODE == 1) {
        Ap = g_Pr; Bp = g_WT + 3l * 512 * 512; Cp = g_hn;
    } else {
        Ap = g_hn; Bp = g_WT + 4l * 512 * 512; Cp = Cout;
    }

    // Global loaders: idx = tid + 256*j covers 512 float4s (128 rows x 4 qwords)
    const float* aptr[2];
    const float* bptr[2];
    int soff[2];
#pragma unroll
    for (int j = 0; j < 2; j++) {
        int idx = tid + 256 * j;
        int ml = idx >> 2;        // 0..127
        int kq = idx & 3;         // float4 index within 16-wide k slab
        int gm = m0 + ml;
        long arow;
        if (MODE == 0) arow = (long)(gm / Nt) * Tfull + (gm % Nt);
        else           arow = gm;
        aptr[j] = Ap + arow * 512 + kq * 4;
        bptr[j] = Bp + (long)(n0 + ml) * 512 + kq * 4;
        soff[j] = ml * PITCH + kq * 4;
    }

    float c[2][8][4];
#pragma unroll
    for (int mt = 0; mt < 2; mt++)
#pragma unroll
        for (int nt = 0; nt < 8; nt++)
#pragma unroll
            for (int q = 0; q < 4; q++) c[mt][nt][q] = 0.0f;

    float4 pa[2], pb[2];
#pragma unroll
    for (int j = 0; j < 2; j++) { pa[j] = *(const float4*)(aptr[j]); pb[j] = *(const float4*)(bptr[j]); }

    // STS chunk 0 -> buf 0 (convert to tf32 bits)
#pragma unroll
    for (int j = 0; j < 2; j++) {
        uint32_t* sa = (uint32_t*)&sm[0][0][soff[j]];
        uint32_t* sb = (uint32_t*)&sm[0][1][soff[j]];
        sa[0] = f2tf(pa[j].x); sa[1] = f2tf(pa[j].y); sa[2] = f2tf(pa[j].z); sa[3] = f2tf(pa[j].w);
        sb[0] = f2tf(pb[j].x); sb[1] = f2tf(pb[j].y); sb[2] = f2tf(pb[j].z); sb[3] = f2tf(pb[j].w);
    }
    __syncthreads();

    const int arow0 = (warpM * 32 + g) * PITCH;        // + mt*16*PITCH, +8*PITCH for hi
    const int brow0 = (warpN * 64 + g) * PITCH;        // + nt*8*PITCH

    for (int kt = 0; kt < 32; kt++) {
        const int buf = kt & 1;
        if (kt < 31) {
            const int co = (kt + 1) * 16;
#pragma unroll
            for (int j = 0; j < 2; j++) { pa[j] = *(const float4*)(aptr[j] + co); pb[j] = *(const float4*)(bptr[j] + co); }
        }

        const uint32_t* As = (const uint32_t*)sm[buf][0];
        const uint32_t* Bs = (const uint32_t*)sm[buf][1];
#pragma unroll
        for (int ks = 0; ks < 2; ks++) {
            const int col = ks * 8 + t;
            uint32_t af[2][4];
#pragma unroll
            for (int mt = 0; mt < 2; mt++) {
                int r0 = arow0 + mt * 16 * PITCH;
                af[mt][0] = As[r0 + col];
                af[mt][1] = As[r0 + 8 * PITCH + col];
                af[mt][2] = As[r0 + col + 4];
                af[mt][3] = As[r0 + 8 * PITCH + col + 4];
            }
            uint32_t bf[8][2];
#pragma unroll
            for (int nt = 0; nt < 8; nt++) {
                int rB = brow0 + nt * 8 * PITCH;
                bf[nt][0] = Bs[rB + col];
                bf[nt][1] = Bs[rB + col + 4];
            }
#pragma unroll
            for (int mt = 0; mt < 2; mt++)
#pragma unroll
                for (int nt = 0; nt < 8; nt++)
                    mma_tf32(c[mt][nt], af[mt], bf[nt]);
        }

        if (kt < 31) {
            const int nbuf = buf ^ 1;
#pragma unroll
            for (int j = 0; j < 2; j++) {
                uint32_t* sa = (uint32_t*)&sm[nbuf][0][soff[j]];
                uint32_t* sb = (uint32_t*)&sm[nbuf][1][soff[j]];
                sa[0] = f2tf(pa[j].x); sa[1] = f2tf(pa[j].y); sa[2] = f2tf(pa[j].z); sa[3] = f2tf(pa[j].w);
                sb[0] = f2tf(pb[j].x); sb[1] = f2tf(pb[j].y); sb[2] = f2tf(pb[j].z); sb[3] = f2tf(pb[j].w);
            }
            __syncthreads();
        }
    }

    // Epilogue: c[mt][nt][rh*2 + 0/1] -> (row = m0+warpM*32+mt*16+g+rh*8, col = n0+warpN*64+nt*8+t*2)
#pragma unroll
    for (int mt = 0; mt < 2; mt++) {
#pragma unroll
        for (int rh = 0; rh < 2; rh++) {
            const int m = m0 + warpM * 32 + mt * 16 + g + rh * 8;
            const int b = (MODE == 1) ? (m / Nt) : 0;
#pragma unroll
            for (int nt = 0; nt < 8; nt++) {
                const int n = n0 + warpN * 64 + nt * 8 + t * 2;
                const long idx = (long)m * 512 + n;
                float v0 = c[mt][nt][rh * 2 + 0];
                float v1 = c[mt][nt][rh * 2 + 1];
                if (MODE == 0) {
                    *(float2*)(Cp + idx) = make_float2(v0, v1);
                } else if (MODE == 1) {
                    float2 zv = *(const float2*)(g_Pz + idx);
                    float2 pv = *(const float2*)(g_Ph + idx);
                    float2 hv = *(const float2*)(h0 + b * 512 + n);
                    float2 bv = *(const float2*)(bias + n);
                    float o0 = (1.0f - zv.x) * hv.x + zv.x * tanhf(pv.x + v0 + bv.x);
                    float o1 = (1.0f - zv.y) * hv.y + zv.y * tanhf(pv.y + v1 + bv.y);
                    *(float2*)(Cp + idx) = make_float2(o0, o1);
                } else {
                    float2 bv = *(const float2*)(bias + n);
                    *(float2*)(Cp + idx) = make_float2(sigmoidf_(v0 + bv.x), sigmoidf_(v1 + bv.y));
                }
            }
        }
    }
}

// ---------------------------------------------------------------------------
__global__ void transpose512(const float* __restrict__ src, float* __restrict__ dst) {
    __shared__ float t[32][33];
    int bx = blockIdx.x * 32, by = blockIdx.y * 32;
#pragma unroll
    for (int i = 0; i < 4; i++)
        t[threadIdx.y + i * 8][threadIdx.x] = src[(long)(by + threadIdx.y + i * 8) * 512 + bx + threadIdx.x];
    __syncthreads();
#pragma unroll
    for (int i = 0; i < 4; i++)
        dst[(long)(bx + threadIdx.y + i * 8) * 512 + by + threadIdx.x] = t[threadIdx.x][threadIdx.y + i * 8];
}

__global__ void hpart_kernel(const float* __restrict__ h0, const float* __restrict__ Wr_h,
                             const float* __restrict__ br, const float* __restrict__ Wz_h,
                             const float* __restrict__ bz) {
    int b = blockIdx.x, n = threadIdx.x;
    float ar = br[n], az = bz[n];
    const float* h0b = h0 + b * Hc;
    for (int k = 0; k < Hc; k++) {
        float h = h0b[k];
        ar = fmaf(h, Wr_h[k * Hc + n], ar);
        az = fmaf(h, Wz_h[k * Hc + n], az);
    }
    g_hpr[b * Hc + n] = ar;
    g_hpz[b * Hc + n] = az;
}

__global__ void ew_rz_kernel(int Nt) {
    long i = (long)blockIdx.x * blockDim.x + threadIdx.x;
    int m = (int)(i >> 9), n = (int)(i & 511);
    int b = m / Nt;
    float r = sigmoidf_(g_Pr[i] + g_hpr[b * 512 + n]);
    float z = sigmoidf_(g_Pz[i] + g_hpz[b * 512 + n]);
    g_Pr[i] = z * r;
    g_Pz[i] = z;
}

__global__ void copy_h0_kernel(const float* __restrict__ h0, float* __restrict__ dst) {
    int i = blockIdx.x * blockDim.x + threadIdx.x;
    dst[i] = h0[i];
}

// ---------------------------------------------------------------------------
extern "C" void kernel_launch(void* const* d_in, const int* in_sizes, int n_in,
                              void* d_out, int out_size) {
    const float* x  = (const float*)d_in[0];
    const float* h0 = (const float*)d_in[1];
    const float* Wr = (const float*)d_in[2];
    const float* br = (const float*)d_in[3];
    const float* Wz = (const float*)d_in[4];
    const float* bz = (const float*)d_in[5];
    const float* Wh = (const float*)d_in[6];
    const float* bh = (const float*)d_in[7];
    const float* Wo = (const float*)d_in[8];
    const float* bo = (const float*)d_in[9];
    float* out = (float*)d_out;

    long os = out_size;
    int Tfull = in_sizes[0] / (Bc * Ic);
    int Nt;
    bool with_h0;
    if (os > (long)Bc * Hc && ((os - (long)Bc * Hc) % ((long)Bc * Oc)) == 0) {
        Nt = (int)((os - (long)Bc * Hc) / ((long)Bc * Oc));
        with_h0 = true;
    } else {
        Nt = (int)(os / ((long)Bc * Oc));
        with_h0 = false;
    }
    int M = Bc * Nt;

    float* wt;
    cudaGetSymbolAddress((void**)&wt, g_WT);

    // Transposed weights: [0]=Wr_x^T [1]=Wz_x^T [2]=Wh_x^T [3]=Wh_h^T [4]=Wo^T
    dim3 tb(32, 8), tg(16, 16);
    transpose512<<<tg, tb>>>(Wr, wt + 0l * 512 * 512);
    transpose512<<<tg, tb>>>(Wz, wt + 1l * 512 * 512);
    transpose512<<<tg, tb>>>(Wh, wt + 2l * 512 * 512);
    transpose512<<<tg, tb>>>(Wh + (long)Ic * Hc, wt + 3l * 512 * 512);
    transpose512<<<tg, tb>>>(Wo, wt + 4l * 512 * 512);

    hpart_kernel<<<Bc, Hc>>>(h0, Wr + (long)Ic * Hc, br, Wz + (long)Ic * Hc, bz);

    // Stage 1: Pr,Pz,Ph = x @ W*_x
    tgemm<0><<<dim3(12, M / 128), 256>>>(x, nullptr, nullptr, nullptr, Nt, Tfull);

    ew_rz_kernel<<<(unsigned)(((long)M * Hc) / 256), 256>>>(Nt);

    // Stage 2: h_new
    tgemm<1><<<dim3(4, M / 128), 256>>>(nullptr, nullptr, bh, h0, Nt, Tfull);

    // Stage 3: out
    tgemm<2><<<dim3(4, M / 128), 256>>>(nullptr, out, bo, nullptr, Nt, Tfull);

    if (with_h0)
        copy_h0_kernel<<<(Bc * Hc) / 256, 256>>>(h0, out + (long)M * Oc);
}

// round 4
// speedup vs baseline: 3.2018x; 1.2319x over previous
#include <cuda_runtime.h>
#include <cuda_bf16.h>
#include <cstdint>
#include <math.h>

#define Bc 64
#define Tc 512
#define Ic 512
#define Hc 512
#define Oc 512

// Scratch
__device__ float    g_z [(long)Bc * Tc * Hc];        // z (fp32)
__device__ float    g_Ph[(long)Bc * Tc * Hc];        // x-part pre-act of h (fp32)
__device__ uint32_t g_zr16[(long)Bc * Tc * Hc / 2];  // zr (bf16x2)
__device__ uint32_t g_hn16[(long)Bc * Tc * Hc / 2];  // h_new (bf16x2)
__device__ float    g_hpr[Bc * Hc];                  // h0@Wr_h + br
__device__ float    g_hpz[Bc * Hc];                  // h0@Wz_h + bz
__device__ __nv_bfloat16 g_WT16[5l * 512 * 512];     // W^T as bf16 [sel][n][k]

__device__ __forceinline__ float sigmoidf_(float x) { return 1.0f / (1.0f + expf(-x)); }

__device__ __forceinline__ uint32_t pk(float lo, float hi) {
    __nv_bfloat162 h = __floats2bfloat162_rn(lo, hi);   // .x = lo
    return *reinterpret_cast<uint32_t*>(&h);
}

__device__ __forceinline__ void mma_bf16(float* c, const uint32_t* a, const uint32_t* b) {
    asm volatile(
        "mma.sync.aligned.m16n8k16.row.col.f32.bf16.bf16.f32 "
        "{%0,%1,%2,%3}, {%4,%5,%6,%7}, {%8,%9}, {%0,%1,%2,%3};"
        : "+f"(c[0]), "+f"(c[1]), "+f"(c[2]), "+f"(c[3])
        : "r"(a[0]), "r"(a[1]), "r"(a[2]), "r"(a[3]), "r"(b[0]), "r"(b[1]));
}

// ---------------------------------------------------------------------------
// bf16 mma.sync GEMM, CTA 128 rows, BK=16, 256 thr, 8 warps (4M x 2N).
// SMEM pitch = 24 bf16 (12 u32) per row: fragment LDS is bank-conflict-free.
//
// MODE 0: A = x (fp32, (b,t) row map), B = {Wr_x,Wz_x,Wh_x}^T bf16, N-tile 64.
//         Epilogue: r,z gates -> writes zr(bf16), z(f32), Ph(f32).
// MODE 1: A = g_zr16 (bf16), B = Wh_h^T, N-tile 128.
//         Epilogue: h1 = tanh(Ph + acc + bh); hn = (1-z)h0 + z*h1 -> bf16.
// MODE 2: A = g_hn16, B = Wo^T, N-tile 128. Epilogue: sigmoid(acc + bo).
// ---------------------------------------------------------------------------
template <int MODE>
__global__ __launch_bounds__(256)
void kgemm(const float* __restrict__ Axf, float* __restrict__ Cout,
           const float* __restrict__ bias, const float* __restrict__ h0,
           int Nt, int Tfull)
{
    constexpr int BROWS = (MODE == 0) ? 192 : 128;  // B tile rows (3 weights x 64 or 1 x 128)
    constexpr int W  = (MODE == 0) ? 3 : 1;
    constexpr int NT = (MODE == 0) ? 4 : 8;
    constexpr int NTILE = (MODE == 0) ? 64 : 128;

    __shared__ uint32_t sm[2][(128 + BROWS) * 12];

    const int tid = threadIdx.x;
    const int wid = tid >> 5, lid = tid & 31;
    const int g = lid >> 2, t = lid & 3;
    const int warpM = wid & 3, warpN = wid >> 2;
    const int m0 = blockIdx.y * 128;
    const int n0 = blockIdx.x * NTILE;

    const uint32_t* WTu = (const uint32_t*)g_WT16;

    // ---- loader setup ----
    // A (fp32 x, MODE 0): 512 float4/chunk -> 2 per thread
    const float* ap32[2];
    int asw32[2];
    // A (bf16 scratch, MODE 1/2): 256 uint4/chunk -> 1 per thread
    const uint32_t* ap16 = nullptr;
    int asw16 = 0;
    if (MODE == 0) {
#pragma unroll
        for (int j = 0; j < 2; j++) {
            int idx = tid + 256 * j;
            int row = idx >> 2, kq = idx & 3;
            int gm = m0 + row;
            long arow = (long)(gm / Nt) * Tfull + (gm % Nt);
            ap32[j] = Axf + arow * 512 + kq * 4;
            asw32[j] = row * 12 + kq * 2;
        }
    } else {
        const uint32_t* A16 = (MODE == 1) ? g_zr16 : g_hn16;
        int row = tid >> 1, half = tid & 1;
        ap16 = A16 + (long)(m0 + row) * 256 + half * 4;
        asw16 = row * 12 + half * 4;
    }

    // B loaders (bf16 weights)
    const uint32_t* bp0;
    const uint32_t* bp1 = nullptr;
    int bsw0, bsw1 = 0;
    if (MODE == 0) {
        {
            int row = tid >> 1, half = tid & 1;       // rows 0..127
            int sel = row >> 6, nr = row & 63;
            bp0 = WTu + (long)sel * 131072 + (n0 + nr) * 256 + half * 4;
            bsw0 = (128 + row) * 12 + half * 4;
        }
        if (tid < 128) {
            int idx = tid + 256;
            int row = idx >> 1, half = idx & 1;       // rows 128..191
            int sel = row >> 6, nr = row & 63;
            bp1 = WTu + (long)sel * 131072 + (n0 + nr) * 256 + half * 4;
            bsw1 = (128 + row) * 12 + half * 4;
        }
    } else {
        const int selw = (MODE == 1) ? 3 : 4;
        int row = tid >> 1, half = tid & 1;
        bp0 = WTu + (long)selw * 131072 + (n0 + row) * 256 + half * 4;
        bsw0 = (128 + row) * 12 + half * 4;
    }

    float c[W][2][NT][4];
#pragma unroll
    for (int w = 0; w < W; w++)
#pragma unroll
        for (int mt = 0; mt < 2; mt++)
#pragma unroll
            for (int nt = 0; nt < NT; nt++)
#pragma unroll
                for (int q = 0; q < 4; q++) c[w][mt][nt][q] = 0.0f;

    // ---- prefetch regs ----
    float4 pa32[2];
    uint4 pa16v, pb0v, pb1v;

    // chunk 0 load + STS
    if (MODE == 0) {
#pragma unroll
        for (int j = 0; j < 2; j++) pa32[j] = *(const float4*)(ap32[j]);
    } else {
        pa16v = *(const uint4*)(ap16);
    }
    pb0v = *(const uint4*)(bp0);
    if (MODE == 0 && tid < 128) pb1v = *(const uint4*)(bp1);

    if (MODE == 0) {
#pragma unroll
        for (int j = 0; j < 2; j++) {
            uint2 v = make_uint2(pk(pa32[j].x, pa32[j].y), pk(pa32[j].z, pa32[j].w));
            *(uint2*)&sm[0][asw32[j]] = v;
        }
    } else {
        *(uint4*)&sm[0][asw16] = pa16v;
    }
    *(uint4*)&sm[0][bsw0] = pb0v;
    if (MODE == 0 && tid < 128) *(uint4*)&sm[0][bsw1] = pb1v;
    __syncthreads();

    const int arow0 = (warpM * 32 + g) * 12;

    for (int kt = 0; kt < 32; kt++) {
        const int buf = kt & 1;
        if (kt < 31) {
            // issue global loads for chunk kt+1 (A advances 16 elems, B 16 bf16 = 8 u32)
            if (MODE == 0) {
                const int co = (kt + 1) * 16;
#pragma unroll
                for (int j = 0; j < 2; j++) pa32[j] = *(const float4*)(ap32[j] + co);
            } else {
                pa16v = *(const uint4*)(ap16 + (kt + 1) * 8);
            }
            pb0v = *(const uint4*)(bp0 + (kt + 1) * 8);
            if (MODE == 0 && tid < 128) pb1v = *(const uint4*)(bp1 + (kt + 1) * 8);
        }

        // ---- MMA on buf ----
        const uint32_t* S = sm[buf];
        uint32_t af[2][4];
#pragma unroll
        for (int mt = 0; mt < 2; mt++) {
            const int r = arow0 + mt * 16 * 12;
            af[mt][0] = S[r + t];
            af[mt][1] = S[r + 96 + t];
            af[mt][2] = S[r + 4 + t];
            af[mt][3] = S[r + 96 + 4 + t];
        }
        uint32_t bf[W][NT][2];
#pragma unroll
        for (int w = 0; w < W; w++)
#pragma unroll
            for (int nt = 0; nt < NT; nt++) {
                const int brow = (MODE == 0) ? (w * 64 + warpN * 32 + nt * 8 + g)
                                             : (warpN * 64 + nt * 8 + g);
                const int rb = (128 + brow) * 12;
                bf[w][nt][0] = S[rb + t];
                bf[w][nt][1] = S[rb + 4 + t];
            }
#pragma unroll
        for (int w = 0; w < W; w++)
#pragma unroll
            for (int mt = 0; mt < 2; mt++)
#pragma unroll
                for (int nt = 0; nt < NT; nt++)
                    mma_bf16(c[w][mt][nt], af[mt], bf[w][nt]);

        if (kt < 31) {
            const int nbuf = buf ^ 1;
            if (MODE == 0) {
#pragma unroll
                for (int j = 0; j < 2; j++) {
                    uint2 v = make_uint2(pk(pa32[j].x, pa32[j].y), pk(pa32[j].z, pa32[j].w));
                    *(uint2*)&sm[nbuf][asw32[j]] = v;
                }
            } else {
                *(uint4*)&sm[nbuf][asw16] = pa16v;
            }
            *(uint4*)&sm[nbuf][bsw0] = pb0v;
            if (MODE == 0 && tid < 128) *(uint4*)&sm[nbuf][bsw1] = pb1v;
            __syncthreads();
        }
    }

    // ---- epilogue ----
#pragma unroll
    for (int mt = 0; mt < 2; mt++) {
#pragma unroll
        for (int rh = 0; rh < 2; rh++) {
            const int m = m0 + warpM * 32 + mt * 16 + g + rh * 8;
            const int b = m / Nt;
#pragma unroll
            for (int nt = 0; nt < NT; nt++) {
                const int n = n0 + warpN * (MODE == 0 ? 32 : 64) + nt * 8 + t * 2;
                const long idx = (long)m * 512 + n;
                if (MODE == 0) {
                    float vr0 = c[0][mt][nt][rh * 2 + 0], vr1 = c[0][mt][nt][rh * 2 + 1];
                    float vz0 = c[1][mt][nt][rh * 2 + 0], vz1 = c[1][mt][nt][rh * 2 + 1];
                    float vh0 = c[2][mt][nt][rh * 2 + 0], vh1 = c[2][mt][nt][rh * 2 + 1];
                    float r0 = sigmoidf_(vr0 + g_hpr[b * 512 + n]);
                    float r1 = sigmoidf_(vr1 + g_hpr[b * 512 + n + 1]);
                    float z0 = sigmoidf_(vz0 + g_hpz[b * 512 + n]);
                    float z1 = sigmoidf_(vz1 + g_hpz[b * 512 + n + 1]);
                    g_zr16[(long)m * 256 + (n >> 1)] = pk(z0 * r0, z1 * r1);
                    *(float2*)(g_z + idx) = make_float2(z0, z1);
                    *(float2*)(g_Ph + idx) = make_float2(vh0, vh1);
                } else if (MODE == 1) {
                    float v0 = c[0][mt][nt][rh * 2 + 0], v1 = c[0][mt][nt][rh * 2 + 1];
                    float2 zv = *(const float2*)(g_z + idx);
                    float2 pv = *(const float2*)(g_Ph + idx);
                    float2 hv = *(const float2*)(h0 + b * 512 + n);
                    float2 bv = *(const float2*)(bias + n);
                    float h10 = tanhf(pv.x + v0 + bv.x);
                    float h11 = tanhf(pv.y + v1 + bv.y);
                    float o0 = (1.0f - zv.x) * hv.x + zv.x * h10;
                    float o1 = (1.0f - zv.y) * hv.y + zv.y * h11;
                    g_hn16[(long)m * 256 + (n >> 1)] = pk(o0, o1);
                } else {
                    float v0 = c[0][mt][nt][rh * 2 + 0], v1 = c[0][mt][nt][rh * 2 + 1];
                    float2 bv = *(const float2*)(bias + n);
                    *(float2*)(Cout + idx) = make_float2(sigmoidf_(v0 + bv.x), sigmoidf_(v1 + bv.y));
                }
            }
        }
    }
}

// ---------------------------------------------------------------------------
// 512x512 transpose + fp32 -> bf16: dst[n][k] = bf16(src[k][n])
// ---------------------------------------------------------------------------
__global__ void transpose512_bf16(const float* __restrict__ src, __nv_bfloat16* __restrict__ dst) {
    __shared__ float t[32][33];
    int bx = blockIdx.x * 32, by = blockIdx.y * 32;
#pragma unroll
    for (int i = 0; i < 4; i++)
        t[threadIdx.y + i * 8][threadIdx.x] = src[(long)(by + threadIdx.y + i * 8) * 512 + bx + threadIdx.x];
    __syncthreads();
#pragma unroll
    for (int i = 0; i < 4; i++)
        dst[(long)(bx + threadIdx.y + i * 8) * 512 + by + threadIdx.x] =
            __float2bfloat16(t[threadIdx.x][threadIdx.y + i * 8]);
}

__global__ void hpart_kernel(const float* __restrict__ h0, const float* __restrict__ Wr_h,
                             const float* __restrict__ br, const float* __restrict__ Wz_h,
                             const float* __restrict__ bz) {
    int b = blockIdx.x, n = threadIdx.x;
    float ar = br[n], az = bz[n];
    const float* h0b = h0 + b * Hc;
    for (int k = 0; k < Hc; k++) {
        float h = h0b[k];
        ar = fmaf(h, Wr_h[k * Hc + n], ar);
        az = fmaf(h, Wz_h[k * Hc + n], az);
    }
    g_hpr[b * Hc + n] = ar;
    g_hpz[b * Hc + n] = az;
}

__global__ void copy_h0_kernel(const float* __restrict__ h0, float* __restrict__ dst) {
    int i = blockIdx.x * blockDim.x + threadIdx.x;
    dst[i] = h0[i];
}

// ---------------------------------------------------------------------------
extern "C" void kernel_launch(void* const* d_in, const int* in_sizes, int n_in,
                              void* d_out, int out_size) {
    const float* x  = (const float*)d_in[0];
    const float* h0 = (const float*)d_in[1];
    const float* Wr = (const float*)d_in[2];
    const float* br = (const float*)d_in[3];
    const float* Wz = (const float*)d_in[4];
    const float* bz = (const float*)d_in[5];
    const float* Wh = (const float*)d_in[6];
    const float* bh = (const float*)d_in[7];
    const float* Wo = (const float*)d_in[8];
    const float* bo = (const float*)d_in[9];
    float* out = (float*)d_out;

    long os = out_size;
    int Tfull = in_sizes[0] / (Bc * Ic);
    int Nt;
    bool with_h0;
    if (os > (long)Bc * Hc && ((os - (long)Bc * Hc) % ((long)Bc * Oc)) == 0) {
        Nt = (int)((os - (long)Bc * Hc) / ((long)Bc * Oc));
        with_h0 = true;
    } else {
        Nt = (int)(os / ((long)Bc * Oc));
        with_h0 = false;
    }
    int M = Bc * Nt;

    __nv_bfloat16* wt;
    cudaGetSymbolAddress((void**)&wt, g_WT16);

    // Transposed bf16 weights: [0]=Wr_x^T [1]=Wz_x^T [2]=Wh_x^T [3]=Wh_h^T [4]=Wo^T
    dim3 tb(32, 8), tg(16, 16);
    transpose512_bf16<<<tg, tb>>>(Wr, wt + 0l * 512 * 512);
    transpose512_bf16<<<tg, tb>>>(Wz, wt + 1l * 512 * 512);
    transpose512_bf16<<<tg, tb>>>(Wh, wt + 2l * 512 * 512);
    transpose512_bf16<<<tg, tb>>>(Wh + (long)Ic * Hc, wt + 3l * 512 * 512);
    transpose512_bf16<<<tg, tb>>>(Wo, wt + 4l * 512 * 512);

    hpart_kernel<<<Bc, Hc>>>(h0, Wr + (long)Ic * Hc, br, Wz + (long)Ic * Hc, bz);

    // Stage 1 (fused r/z/zr gates): 3 GEMMs + elementwise in one kernel
    kgemm<0><<<dim3(8, M / 128), 256>>>(x, nullptr, nullptr, nullptr, Nt, Tfull);

    // Stage 2: h_new = (1-z)h0 + z*tanh(Ph + zr@Wh_h + bh)
    kgemm<1><<<dim3(4, M / 128), 256>>>(nullptr, nullptr, bh, h0, Nt, Tfull);

    // Stage 3: out = sigmoid(hn@Wo + bo)
    kgemm<2><<<dim3(4, M / 128), 256>>>(nullptr, out, bo, nullptr, Nt, Tfull);

    if (with_h0)
        copy_h0_kernel<<<(Bc * Hc) / 256, 256>>>(h0, out + (long)M * Oc);
}

// round 5
// speedup vs baseline: 4.0678x; 1.2705x over previous
#include <cuda_runtime.h>
#include <cuda_bf16.h>
#include <cstdint>
#include <math.h>

#define Bc 64
#define Tc 512
#define Ic 512
#define Hc 512
#define Oc 512

// Scratch
__device__ float    g_z [(long)Bc * Tc * Hc];        // z (fp32)
__device__ float    g_Ph[(long)Bc * Tc * Hc];        // x-part pre-act of h (fp32)
__device__ uint32_t g_x16 [(long)Bc * Tc * Ic / 2];  // x as bf16x2
__device__ uint32_t g_zr16[(long)Bc * Tc * Hc / 2];  // zr (bf16x2)
__device__ uint32_t g_hn16[(long)Bc * Tc * Hc / 2];  // h_new (bf16x2)
__device__ float    g_hpr[Bc * Hc];
__device__ float    g_hpz[Bc * Hc];
__device__ __nv_bfloat16 g_WT16[5l * 512 * 512];     // W^T bf16 [sel][n][k]

__device__ __forceinline__ float sigmoidf_(float x) { return 1.0f / (1.0f + expf(-x)); }

__device__ __forceinline__ uint32_t pk(float lo, float hi) {
    __nv_bfloat162 h = __floats2bfloat162_rn(lo, hi);
    return *reinterpret_cast<uint32_t*>(&h);
}

__device__ __forceinline__ uint32_t smem_u32(const void* p) {
    uint32_t a;
    asm("{ .reg .u64 t; cvta.to.shared.u64 t, %1; cvt.u32.u64 %0, t; }" : "=r"(a) : "l"(p));
    return a;
}

__device__ __forceinline__ void mma_bf16(float* c, const uint32_t* a, const uint32_t* b) {
    asm volatile(
        "mma.sync.aligned.m16n8k16.row.col.f32.bf16.bf16.f32 "
        "{%0,%1,%2,%3}, {%4,%5,%6,%7}, {%8,%9}, {%0,%1,%2,%3};"
        : "+f"(c[0]), "+f"(c[1]), "+f"(c[2]), "+f"(c[3])
        : "r"(a[0]), "r"(a[1]), "r"(a[2]), "r"(a[3]), "r"(b[0]), "r"(b[1]));
}

#define CP16(saddr, gptr) asm volatile("cp.async.cg.shared.global [%0], [%1], 16;" :: "r"(saddr), "l"(gptr))
#define CP_COMMIT()       asm volatile("cp.async.commit_group;" ::: "memory")
#define CP_WAIT1()        asm volatile("cp.async.wait_group 1;" ::: "memory")
#define CP_WAIT0()        asm volatile("cp.async.wait_group 0;" ::: "memory")

// ---------------------------------------------------------------------------
// bf16 mma.sync GEMM, CTA 128 rows, BK=32, cp.async 3-stage, 256 thr,
// 8 warps (4M x 2N). SMEM row pitch = 20 u32 (conflict-free fragments).
//
// MODE 0: A = g_x16 ((b,t) map), B = {Wr_x,Wz_x,Wh_x}^T, N-tile 64, 3 accums.
//         Epi: r,z -> zr(bf16), z(f32), Ph(f32).
// MODE 1: A = g_zr16, B = Wh_h^T, N-tile 128. Epi: h_new -> bf16.
// MODE 2: A = g_hn16, B = Wo^T,  N-tile 128. Epi: sigmoid -> out.
// ---------------------------------------------------------------------------
template <int MODE>
__global__ __launch_bounds__(256, (MODE == 0) ? 1 : 2)
void kgemm(float* __restrict__ Cout, const float* __restrict__ bias,
           const float* __restrict__ h0, int Nt, int Tfull)
{
    constexpr int BROWS = (MODE == 0) ? 192 : 128;
    constexpr int W     = (MODE == 0) ? 3 : 1;
    constexpr int NT    = (MODE == 0) ? 4 : 8;
    constexpr int NTILE = (MODE == 0) ? 64 : 128;
    constexpr int ROWS  = 128 + BROWS;
    constexpr int STG   = ROWS * 20;              // u32 per stage
    constexpr int NCHT  = (ROWS * 4) / 256;       // 16B chunks per thread (5 / 4)

    extern __shared__ uint32_t sm[];
    const uint32_t sbase = smem_u32(sm);

    const int tid = threadIdx.x;
    const int wid = tid >> 5, lid = tid & 31;
    const int g = lid >> 2, t = lid & 3;
    const int warpM = wid & 3, warpN = wid >> 2;
    const int m0 = blockIdx.y * 128;
    const int n0 = blockIdx.x * NTILE;

    const uint32_t* WTu = (const uint32_t*)g_WT16;
    const uint32_t* Ap = (MODE == 0) ? g_x16 : (MODE == 1) ? g_zr16 : g_hn16;
    constexpr int selw = (MODE == 1) ? 3 : 4;

    // ---- chunk map: c<512 -> A (row=c>>2,q=c&3), else B ----
    const uint32_t* gp[NCHT];
    int soff[NCHT];
#pragma unroll
    for (int i = 0; i < NCHT; i++) {
        int c = tid + 256 * i;
        if (c < 512) {
            int row = c >> 2, q = c & 3;
            int gm = m0 + row;
            long arow = (MODE == 0) ? ((long)(gm / Nt) * Tfull + (gm % Nt)) : gm;
            gp[i] = Ap + arow * 256 + q * 4;
            soff[i] = row * 20 + q * 4;
        } else {
            int cc = c - 512;
            int brow = cc >> 2, q = cc & 3;
            long wrow;
            if (MODE == 0) {
                int sel = brow >> 6, nr = brow & 63;
                wrow = (long)sel * 512 + n0 + nr;
            } else {
                wrow = (long)selw * 512 + n0 + brow;
            }
            gp[i] = WTu + wrow * 256 + q * 4;
            soff[i] = (128 + brow) * 20 + q * 4;
        }
    }

    float c[W][2][NT][4];
#pragma unroll
    for (int w = 0; w < W; w++)
#pragma unroll
        for (int mt = 0; mt < 2; mt++)
#pragma unroll
            for (int nt = 0; nt < NT; nt++)
#pragma unroll
                for (int q = 0; q < 4; q++) c[w][mt][nt][q] = 0.0f;

    // ---- prologue: stages 0,1 ----
#pragma unroll
    for (int i = 0; i < NCHT; i++) CP16(sbase + soff[i] * 4, gp[i]);
    CP_COMMIT();
#pragma unroll
    for (int i = 0; i < NCHT; i++) CP16(sbase + (STG + soff[i]) * 4, gp[i] + 16);
    CP_COMMIT();
    CP_WAIT1();
    __syncthreads();

    // ---- mainloop: 16 chunks of BK=32 ----
    for (int kt = 0; kt < 16; kt++) {
        if (kt < 14) {
            const int b2 = ((kt + 2) % 3) * STG;
            const int go = (kt + 2) * 16;
#pragma unroll
            for (int i = 0; i < NCHT; i++) CP16(sbase + (b2 + soff[i]) * 4, gp[i] + go);
            CP_COMMIT();
        }

        const uint32_t* S = sm + (kt % 3) * STG;
#pragma unroll
        for (int ks = 0; ks < 2; ks++) {
            const int kc = ks * 8 + t;
            uint32_t af[2][4];
#pragma unroll
            for (int mt = 0; mt < 2; mt++) {
                const int r = (warpM * 32 + mt * 16 + g) * 20;
                af[mt][0] = S[r + kc];
                af[mt][1] = S[r + 160 + kc];
                af[mt][2] = S[r + kc + 4];
                af[mt][3] = S[r + 160 + kc + 4];
            }
            uint32_t bf[W][NT][2];
#pragma unroll
            for (int w = 0; w < W; w++)
#pragma unroll
                for (int nt = 0; nt < NT; nt++) {
                    const int brow = (MODE == 0) ? (w * 64 + warpN * 32 + nt * 8 + g)
                                                 : (warpN * 64 + nt * 8 + g);
                    const int rb = (128 + brow) * 20;
                    bf[w][nt][0] = S[rb + kc];
                    bf[w][nt][1] = S[rb + kc + 4];
                }
#pragma unroll
            for (int w = 0; w < W; w++)
#pragma unroll
                for (int mt = 0; mt < 2; mt++)
#pragma unroll
                    for (int nt = 0; nt < NT; nt++)
                        mma_bf16(c[w][mt][nt], af[mt], bf[w][nt]);
        }

        if (kt < 15) {
            if (kt < 14) CP_WAIT1(); else CP_WAIT0();
            __syncthreads();
        }
    }

    // ---- epilogue ----
#pragma unroll
    for (int mt = 0; mt < 2; mt++) {
#pragma unroll
        for (int rh = 0; rh < 2; rh++) {
            const int m = m0 + warpM * 32 + mt * 16 + g + rh * 8;
            const int b = m / Nt;
#pragma unroll
            for (int nt = 0; nt < NT; nt++) {
                const int n = n0 + warpN * (MODE == 0 ? 32 : 64) + nt * 8 + t * 2;
                const long idx = (long)m * 512 + n;
                if (MODE == 0) {
                    float vr0 = c[0][mt][nt][rh * 2 + 0], vr1 = c[0][mt][nt][rh * 2 + 1];
                    float vz0 = c[1 % W][mt][nt][rh * 2 + 0], vz1 = c[1 % W][mt][nt][rh * 2 + 1];
                    float vh0 = c[2 % W][mt][nt][rh * 2 + 0], vh1 = c[2 % W][mt][nt][rh * 2 + 1];
                    float r0 = sigmoidf_(vr0 + g_hpr[b * 512 + n]);
                    float r1 = sigmoidf_(vr1 + g_hpr[b * 512 + n + 1]);
                    float z0 = sigmoidf_(vz0 + g_hpz[b * 512 + n]);
                    float z1 = sigmoidf_(vz1 + g_hpz[b * 512 + n + 1]);
                    g_zr16[(long)m * 256 + (n >> 1)] = pk(z0 * r0, z1 * r1);
                    *(float2*)(g_z + idx) = make_float2(z0, z1);
                    *(float2*)(g_Ph + idx) = make_float2(vh0, vh1);
                } else if (MODE == 1) {
                    float v0 = c[0][mt][nt][rh * 2 + 0], v1 = c[0][mt][nt][rh * 2 + 1];
                    float2 zv = *(const float2*)(g_z + idx);
                    float2 pv = *(const float2*)(g_Ph + idx);
                    float2 hv = *(const float2*)(h0 + b * 512 + n);
                    float2 bv = *(const float2*)(bias + n);
                    float o0 = (1.0f - zv.x) * hv.x + zv.x * tanhf(pv.x + v0 + bv.x);
                    float o1 = (1.0f - zv.y) * hv.y + zv.y * tanhf(pv.y + v1 + bv.y);
                    g_hn16[(long)m * 256 + (n >> 1)] = pk(o0, o1);
                } else {
                    float v0 = c[0][mt][nt][rh * 2 + 0], v1 = c[0][mt][nt][rh * 2 + 1];
                    float2 bv = *(const float2*)(bias + n);
                    *(float2*)(Cout + idx) = make_float2(sigmoidf_(v0 + bv.x), sigmoidf_(v1 + bv.y));
                }
            }
        }
    }
}

// ---------------------------------------------------------------------------
__global__ void cvt_x_kernel(const float* __restrict__ src, uint32_t* __restrict__ dst) {
    long i = (long)blockIdx.x * blockDim.x + threadIdx.x;
    float4 v = ((const float4*)src)[i];
    ((uint2*)dst)[i] = make_uint2(pk(v.x, v.y), pk(v.z, v.w));
}

__global__ void transpose512_bf16(const float* __restrict__ src, __nv_bfloat16* __restrict__ dst) {
    __shared__ float t[32][33];
    int bx = blockIdx.x * 32, by = blockIdx.y * 32;
#pragma unroll
    for (int i = 0; i < 4; i++)
        t[threadIdx.y + i * 8][threadIdx.x] = src[(long)(by + threadIdx.y + i * 8) * 512 + bx + threadIdx.x];
    __syncthreads();
#pragma unroll
    for (int i = 0; i < 4; i++)
        dst[(long)(bx + threadIdx.y + i * 8) * 512 + by + threadIdx.x] =
            __float2bfloat16(t[threadIdx.x][threadIdx.y + i * 8]);
}

__global__ void hpart_kernel(const float* __restrict__ h0, const float* __restrict__ Wr_h,
                             const float* __restrict__ br, const float* __restrict__ Wz_h,
                             const float* __restrict__ bz) {
    int b = blockIdx.x, n = threadIdx.x;
    float ar = br[n], az = bz[n];
    const float* h0b = h0 + b * Hc;
    for (int k = 0; k < Hc; k++) {
        float h = h0b[k];
        ar = fmaf(h, Wr_h[k * Hc + n], ar);
        az = fmaf(h, Wz_h[k * Hc + n], az);
    }
    g_hpr[b * Hc + n] = ar;
    g_hpz[b * Hc + n] = az;
}

__global__ void copy_h0_kernel(const float* __restrict__ h0, float* __restrict__ dst) {
    int i = blockIdx.x * blockDim.x + threadIdx.x;
    dst[i] = h0[i];
}

// ---------------------------------------------------------------------------
extern "C" void kernel_launch(void* const* d_in, const int* in_sizes, int n_in,
                              void* d_out, int out_size) {
    const float* x  = (const float*)d_in[0];
    const float* h0 = (const float*)d_in[1];
    const float* Wr = (const float*)d_in[2];
    const float* br = (const float*)d_in[3];
    const float* Wz = (const float*)d_in[4];
    const float* bz = (const float*)d_in[5];
    const float* Wh = (const float*)d_in[6];
    const float* bh = (const float*)d_in[7];
    const float* Wo = (const float*)d_in[8];
    const float* bo = (const float*)d_in[9];
    float* out = (float*)d_out;

    long os = out_size;
    int Tfull = in_sizes[0] / (Bc * Ic);
    int Nt;
    bool with_h0;
    if (os > (long)Bc * Hc && ((os - (long)Bc * Hc) % ((long)Bc * Oc)) == 0) {
        Nt = (int)((os - (long)Bc * Hc) / ((long)Bc * Oc));
        with_h0 = true;
    } else {
        Nt = (int)(os / ((long)Bc * Oc));
        with_h0 = false;
    }
    int M = Bc * Nt;

    const int smem0 = 320 * 20 * 3 * 4;   // 76800 B
    const int smem12 = 256 * 20 * 3 * 4;  // 61440 B
    cudaFuncSetAttribute(kgemm<0>, cudaFuncAttributeMaxDynamicSharedMemorySize, smem0);
    cudaFuncSetAttribute(kgemm<1>, cudaFuncAttributeMaxDynamicSharedMemorySize, smem12);
    cudaFuncSetAttribute(kgemm<2>, cudaFuncAttributeMaxDynamicSharedMemorySize, smem12);

    __nv_bfloat16* wt;
    cudaGetSymbolAddress((void**)&wt, g_WT16);
    uint32_t* x16;
    cudaGetSymbolAddress((void**)&x16, g_x16);

    // Weights^T (bf16): [0]=Wr_x [1]=Wz_x [2]=Wh_x [3]=Wh_h [4]=Wo
    dim3 tb(32, 8), tg(16, 16);
    transpose512_bf16<<<tg, tb>>>(Wr, wt + 0l * 512 * 512);
    transpose512_bf16<<<tg, tb>>>(Wz, wt + 1l * 512 * 512);
    transpose512_bf16<<<tg, tb>>>(Wh, wt + 2l * 512 * 512);
    transpose512_bf16<<<tg, tb>>>(Wh + (long)Ic * Hc, wt + 3l * 512 * 512);
    transpose512_bf16<<<tg, tb>>>(Wo, wt + 4l * 512 * 512);

    // x -> bf16 (full tensor; row map applied at GEMM A-load)
    long x4 = (long)in_sizes[0] / 4;
    cvt_x_kernel<<<(unsigned)(x4 / 256), 256>>>(x, x16);

    hpart_kernel<<<Bc, Hc>>>(h0, Wr + (long)Ic * Hc, br, Wz + (long)Ic * Hc, bz);

    // Stage 1 (fused gates)
    kgemm<0><<<dim3(8, M / 128), 256, smem0>>>(nullptr, nullptr, nullptr, Nt, Tfull);
    // Stage 2: h_new
    kgemm<1><<<dim3(4, M / 128), 256, smem12>>>(nullptr, bh, h0, Nt, Tfull);
    // Stage 3: out
    kgemm<2><<<dim3(4, M / 128), 256, smem12>>>(out, bo, nullptr, Nt, Tfull);

    if (with_h0)
        copy_h0_kernel<<<(Bc * Hc) / 256, 256>>>(h0, out + (long)M * Oc);
}

// round 6
// speedup vs baseline: 4.2215x; 1.0378x over previous
#include <cuda_runtime.h>
#include <cuda_bf16.h>
#include <cstdint>
#include <math.h>

#define Bc 64
#define Tc 512
#define Ic 512
#define Hc 512
#define Oc 512

// Scratch
__device__ float    g_z [(long)Bc * Tc * Hc];        // z (fp32)
__device__ float    g_Ph[(long)Bc * Tc * Hc];        // x-part pre-act of h (fp32)
__device__ uint32_t g_x16 [(long)Bc * Tc * Ic / 2];  // x as bf16x2
__device__ uint32_t g_zr16[(long)Bc * Tc * Hc / 2];  // zr (bf16x2)
__device__ uint32_t g_hn16[(long)Bc * Tc * Hc / 2];  // h_new (bf16x2)
__device__ float    g_hpr[Bc * Hc];
__device__ float    g_hpz[Bc * Hc];
__device__ __nv_bfloat16 g_WT16[5l * 512 * 512];     // W^T bf16 [sel][n][k]

__device__ __forceinline__ float sigmoidf_(float x) { return 1.0f / (1.0f + expf(-x)); }

__device__ __forceinline__ uint32_t pk(float lo, float hi) {
    __nv_bfloat162 h = __floats2bfloat162_rn(lo, hi);
    return *reinterpret_cast<uint32_t*>(&h);
}

__device__ __forceinline__ uint32_t smem_u32(const void* p) {
    uint32_t a;
    asm("{ .reg .u64 t; cvta.to.shared.u64 t, %1; cvt.u32.u64 %0, t; }" : "=r"(a) : "l"(p));
    return a;
}

__device__ __forceinline__ void mma_bf16(float* c, const uint32_t* a, const uint32_t* b) {
    asm volatile(
        "mma.sync.aligned.m16n8k16.row.col.f32.bf16.bf16.f32 "
        "{%0,%1,%2,%3}, {%4,%5,%6,%7}, {%8,%9}, {%0,%1,%2,%3};"
        : "+f"(c[0]), "+f"(c[1]), "+f"(c[2]), "+f"(c[3])
        : "r"(a[0]), "r"(a[1]), "r"(a[2]), "r"(a[3]), "r"(b[0]), "r"(b[1]));
}

__device__ __forceinline__ void ldm4(uint32_t* r, uint32_t addr) {
    asm volatile("ldmatrix.sync.aligned.m8n8.x4.shared.b16 {%0,%1,%2,%3}, [%4];"
                 : "=r"(r[0]), "=r"(r[1]), "=r"(r[2]), "=r"(r[3]) : "r"(addr));
}

#define CP16(saddr, gptr) asm volatile("cp.async.cg.shared.global [%0], [%1], 16;" :: "r"(saddr), "l"(gptr))
#define CP_COMMIT()       asm volatile("cp.async.commit_group;" ::: "memory")
#define CP_WAIT1()        asm volatile("cp.async.wait_group 1;" ::: "memory")
#define CP_WAIT0()        asm volatile("cp.async.wait_group 0;" ::: "memory")

// ---------------------------------------------------------------------------
// bf16 mma.sync GEMM, CTA 128 rows, BK=32, cp.async 3-stage, ldmatrix frags,
// 256 thr, 8 warps (4M x 2N). SMEM row pitch = 20 u32.
//
// MODE 0: A = g_x16 ((b,t) map), B = {Wr_x,Wz_x,Wh_x}^T, N-tile 64, 3 accums.
//         Epi: r,z -> zr(bf16), z(f32), Ph(f32).
// MODE 1: A = g_zr16, B = Wh_h^T, N-tile 128. Epi: h_new -> bf16.
// MODE 2: A = g_hn16, B = Wo^T,  N-tile 128. Epi: sigmoid -> out.
// ---------------------------------------------------------------------------
template <int MODE>
__global__ __launch_bounds__(256, (MODE == 0) ? 1 : 2)
void kgemm(float* __restrict__ Cout, const float* __restrict__ bias,
           const float* __restrict__ h0, int Nt, int Tfull)
{
    constexpr int BROWS = (MODE == 0) ? 192 : 128;
    constexpr int W     = (MODE == 0) ? 3 : 1;
    constexpr int NT    = (MODE == 0) ? 4 : 8;
    constexpr int NTILE = (MODE == 0) ? 64 : 128;
    constexpr int NGRP  = (MODE == 0) ? 6 : 4;       // ldmatrix B groups (2 n-tiles each)
    constexpr int ROWS  = 128 + BROWS;
    constexpr int STG   = ROWS * 20;                 // u32 per stage
    constexpr int NCHT  = (ROWS * 4) / 256;

    extern __shared__ uint32_t sm[];
    const uint32_t sbase = smem_u32(sm);

    const int tid = threadIdx.x;
    const int wid = tid >> 5, lid = tid & 31;
    const int g = lid >> 2, t = lid & 3;
    const int warpM = wid & 3, warpN = wid >> 2;
    const int m0 = blockIdx.y * 128;
    const int n0 = blockIdx.x * NTILE;

    const uint32_t* WTu = (const uint32_t*)g_WT16;
    const uint32_t* Ap = (MODE == 0) ? g_x16 : (MODE == 1) ? g_zr16 : g_hn16;
    constexpr int selw = (MODE == 1) ? 3 : 4;

    // ---- cp.async chunk map ----
    const uint32_t* gp[NCHT];
    int soff[NCHT];
#pragma unroll
    for (int i = 0; i < NCHT; i++) {
        int c = tid + 256 * i;
        if (c < 512) {
            int row = c >> 2, q = c & 3;
            int gm = m0 + row;
            long arow = (MODE == 0) ? ((long)(gm / Nt) * Tfull + (gm % Nt)) : gm;
            gp[i] = Ap + arow * 256 + q * 4;
            soff[i] = row * 20 + q * 4;
        } else {
            int cc = c - 512;
            int brow = cc >> 2, q = cc & 3;
            long wrow;
            if (MODE == 0) {
                int sel = brow >> 6, nr = brow & 63;
                wrow = (long)sel * 512 + n0 + nr;
            } else {
                wrow = (long)selw * 512 + n0 + brow;
            }
            gp[i] = WTu + wrow * 256 + q * 4;
            soff[i] = (128 + brow) * 20 + q * 4;
        }
    }

    // ---- ldmatrix per-lane base addresses (byte) ----
    // A x4: matrices = [rows m+0..7 kh0][rows m+8..15 kh0][rows m+0..7 kh1][rows m+8..15 kh1]
    const int a_row = warpM * 32 + (lid & 15);
    const int a_kh  = (lid & 16) ? 4 : 0;
    const uint32_t a_addr = sbase + (uint32_t)(a_row * 20 + a_kh) * 4;
    // B x4: matrices = [rows nb+0..7 kh0][rows nb+0..7 kh1][rows nb+8..15 kh0][rows nb+8..15 kh1]
    const int b_row = ((lid & 16) ? 8 : 0) + (lid & 7);
    const int b_kh  = (lid & 8) ? 4 : 0;
    const uint32_t b_addr = sbase + (uint32_t)((128 + b_row) * 20 + b_kh) * 4;

    int bgrp_off[NGRP];   // brow_base * 80 bytes
#pragma unroll
    for (int gb = 0; gb < NGRP; gb++) {
        int base = (MODE == 0) ? ((gb >> 1) * 64 + warpN * 32 + (gb & 1) * 16)
                               : (warpN * 64 + gb * 16);
        bgrp_off[gb] = base * 80;
    }

    float c[W][2][NT][4];
#pragma unroll
    for (int w = 0; w < W; w++)
#pragma unroll
        for (int mt = 0; mt < 2; mt++)
#pragma unroll
            for (int nt = 0; nt < NT; nt++)
#pragma unroll
                for (int q = 0; q < 4; q++) c[w][mt][nt][q] = 0.0f;

    // ---- prologue: stages 0,1 ----
#pragma unroll
    for (int i = 0; i < NCHT; i++) CP16(sbase + soff[i] * 4, gp[i]);
    CP_COMMIT();
#pragma unroll
    for (int i = 0; i < NCHT; i++) CP16(sbase + (STG + soff[i]) * 4, gp[i] + 16);
    CP_COMMIT();
    CP_WAIT1();
    __syncthreads();

    // ---- mainloop ----
    for (int kt = 0; kt < 16; kt++) {
        if (kt < 14) {
            const int b2 = ((kt + 2) % 3) * STG;
            const int go = (kt + 2) * 16;
#pragma unroll
            for (int i = 0; i < NCHT; i++) CP16(sbase + (b2 + soff[i]) * 4, gp[i] + go);
            CP_COMMIT();
        }

        const uint32_t stoff = (uint32_t)((kt % 3) * STG) * 4;
#pragma unroll
        for (int ks = 0; ks < 2; ks++) {
            // A frags: af4[mt] = {a0,a1,a2,a3}
            uint32_t af4[2][4];
#pragma unroll
            for (int mt = 0; mt < 2; mt++)
                ldm4(af4[mt], a_addr + stoff + mt * 1280 + ks * 32);
            // B frags: bf4[gb] = {b0(e), b1(e), b0(o), b1(o)}
            uint32_t bf4[NGRP][4];
#pragma unroll
            for (int gb = 0; gb < NGRP; gb++)
                ldm4(bf4[gb], b_addr + stoff + bgrp_off[gb] + ks * 32);

#pragma unroll
            for (int w = 0; w < W; w++)
#pragma unroll
                for (int mt = 0; mt < 2; mt++)
#pragma unroll
                    for (int nt = 0; nt < NT; nt++) {
                        const int gb = (MODE == 0) ? (w * 2 + (nt >> 1)) : (nt >> 1);
                        mma_bf16(c[w][mt][nt], af4[mt], &bf4[gb][(nt & 1) * 2]);
                    }
        }

        if (kt < 15) {
            if (kt < 14) CP_WAIT1(); else CP_WAIT0();
            __syncthreads();
        }
    }

    // ---- epilogue ----
#pragma unroll
    for (int mt = 0; mt < 2; mt++) {
#pragma unroll
        for (int rh = 0; rh < 2; rh++) {
            const int m = m0 + warpM * 32 + mt * 16 + g + rh * 8;
            const int b = m / Nt;
#pragma unroll
            for (int nt = 0; nt < NT; nt++) {
                const int n = n0 + warpN * (MODE == 0 ? 32 : 64) + nt * 8 + t * 2;
                const long idx = (long)m * 512 + n;
                if (MODE == 0) {
                    float vr0 = c[0][mt][nt][rh * 2 + 0], vr1 = c[0][mt][nt][rh * 2 + 1];
                    float vz0 = c[1 % W][mt][nt][rh * 2 + 0], vz1 = c[1 % W][mt][nt][rh * 2 + 1];
                    float vh0 = c[2 % W][mt][nt][rh * 2 + 0], vh1 = c[2 % W][mt][nt][rh * 2 + 1];
                    float r0 = sigmoidf_(vr0 + g_hpr[b * 512 + n]);
                    float r1 = sigmoidf_(vr1 + g_hpr[b * 512 + n + 1]);
                    float z0 = sigmoidf_(vz0 + g_hpz[b * 512 + n]);
                    float z1 = sigmoidf_(vz1 + g_hpz[b * 512 + n + 1]);
                    g_zr16[(long)m * 256 + (n >> 1)] = pk(z0 * r0, z1 * r1);
                    *(float2*)(g_z + idx) = make_float2(z0, z1);
                    *(float2*)(g_Ph + idx) = make_float2(vh0, vh1);
                } else if (MODE == 1) {
                    float v0 = c[0][mt][nt][rh * 2 + 0], v1 = c[0][mt][nt][rh * 2 + 1];
                    float2 zv = *(const float2*)(g_z + idx);
                    float2 pv = *(const float2*)(g_Ph + idx);
                    float2 hv = *(const float2*)(h0 + b * 512 + n);
                    float2 bv = *(const float2*)(bias + n);
                    float o0 = (1.0f - zv.x) * hv.x + zv.x * tanhf(pv.x + v0 + bv.x);
                    float o1 = (1.0f - zv.y) * hv.y + zv.y * tanhf(pv.y + v1 + bv.y);
                    g_hn16[(long)m * 256 + (n >> 1)] = pk(o0, o1);
                } else {
                    float v0 = c[0][mt][nt][rh * 2 + 0], v1 = c[0][mt][nt][rh * 2 + 1];
                    float2 bv = *(const float2*)(bias + n);
                    *(float2*)(Cout + idx) = make_float2(sigmoidf_(v0 + bv.x), sigmoidf_(v1 + bv.y));
                }
            }
        }
    }
}

// ---------------------------------------------------------------------------
__global__ void cvt_x_kernel(const float* __restrict__ src, uint32_t* __restrict__ dst) {
    long i = (long)blockIdx.x * blockDim.x + threadIdx.x;
    float4 v = ((const float4*)src)[i];
    ((uint2*)dst)[i] = make_uint2(pk(v.x, v.y), pk(v.z, v.w));
}

// All 5 weight transposes in one launch (z = which weight)
__global__ void transpose_all_bf16(const float* __restrict__ Wr, const float* __restrict__ Wz,
                                   const float* __restrict__ Wh, const float* __restrict__ Wo,
                                   __nv_bfloat16* __restrict__ dst) {
    __shared__ float tbuf[32][33];
    const int sel = blockIdx.z;
    const float* src = (sel == 0) ? Wr : (sel == 1) ? Wz : (sel == 2) ? Wh
                     : (sel == 3) ? (Wh + (long)Ic * Hc) : Wo;
    __nv_bfloat16* d = dst + (long)sel * 512 * 512;
    int bx = blockIdx.x * 32, by = blockIdx.y * 32;
#pragma unroll
    for (int i = 0; i < 4; i++)
        tbuf[threadIdx.y + i * 8][threadIdx.x] = src[(long)(by + threadIdx.y + i * 8) * 512 + bx + threadIdx.x];
    __syncthreads();
#pragma unroll
    for (int i = 0; i < 4; i++)
        d[(long)(bx + threadIdx.y + i * 8) * 512 + by + threadIdx.x] =
            __float2bfloat16(tbuf[threadIdx.x][threadIdx.y + i * 8]);
}

__global__ void hpart_kernel(const float* __restrict__ h0, const float* __restrict__ Wr_h,
                             const float* __restrict__ br, const float* __restrict__ Wz_h,
                             const float* __restrict__ bz) {
    int b = blockIdx.x, n = threadIdx.x;
    float ar = br[n], az = bz[n];
    const float* h0b = h0 + b * Hc;
    for (int k = 0; k < Hc; k++) {
        float h = h0b[k];
        ar = fmaf(h, Wr_h[k * Hc + n], ar);
        az = fmaf(h, Wz_h[k * Hc + n], az);
    }
    g_hpr[b * Hc + n] = ar;
    g_hpz[b * Hc + n] = az;
}

__global__ void copy_h0_kernel(const float* __restrict__ h0, float* __restrict__ dst) {
    int i = blockIdx.x * blockDim.x + threadIdx.x;
    dst[i] = h0[i];
}

// ---------------------------------------------------------------------------
extern "C" void kernel_launch(void* const* d_in, const int* in_sizes, int n_in,
                              void* d_out, int out_size) {
    const float* x  = (const float*)d_in[0];
    const float* h0 = (const float*)d_in[1];
    const float* Wr = (const float*)d_in[2];
    const float* br = (const float*)d_in[3];
    const float* Wz = (const float*)d_in[4];
    const float* bz = (const float*)d_in[5];
    const float* Wh = (const float*)d_in[6];
    const float* bh = (const float*)d_in[7];
    const float* Wo = (const float*)d_in[8];
    const float* bo = (const float*)d_in[9];
    float* out = (float*)d_out;

    long os = out_size;
    int Tfull = in_sizes[0] / (Bc * Ic);
    int Nt;
    bool with_h0;
    if (os > (long)Bc * Hc && ((os - (long)Bc * Hc) % ((long)Bc * Oc)) == 0) {
        Nt = (int)((os - (long)Bc * Hc) / ((long)Bc * Oc));
        with_h0 = true;
    } else {
        Nt = (int)(os / ((long)Bc * Oc));
        with_h0 = false;
    }
    int M = Bc * Nt;

    const int smem0 = 320 * 20 * 3 * 4;
    const int smem12 = 256 * 20 * 3 * 4;
    cudaFuncSetAttribute(kgemm<0>, cudaFuncAttributeMaxDynamicSharedMemorySize, smem0);
    cudaFuncSetAttribute(kgemm<1>, cudaFuncAttributeMaxDynamicSharedMemorySize, smem12);
    cudaFuncSetAttribute(kgemm<2>, cudaFuncAttributeMaxDynamicSharedMemorySize, smem12);

    __nv_bfloat16* wt;
    cudaGetSymbolAddress((void**)&wt, g_WT16);
    uint32_t* x16;
    cudaGetSymbolAddress((void**)&x16, g_x16);

    transpose_all_bf16<<<dim3(16, 16, 5), dim3(32, 8)>>>(Wr, Wz, Wh, Wo, wt);

    long x4 = (long)in_sizes[0] / 4;
    cvt_x_kernel<<<(unsigned)(x4 / 256), 256>>>(x, x16);

    hpart_kernel<<<Bc, Hc>>>(h0, Wr + (long)Ic * Hc, br, Wz + (long)Ic * Hc, bz);

    kgemm<0><<<dim3(8, M / 128), 256, smem0>>>(nullptr, nullptr, nullptr, Nt, Tfull);
    kgemm<1><<<dim3(4, M / 128), 256, smem12>>>(nullptr, bh, h0, Nt, Tfull);
    kgemm<2><<<dim3(4, M / 128), 256, smem12>>>(out, bo, nullptr, Nt, Tfull);

    if (with_h0)
        copy_h0_kernel<<<(Bc * Hc) / 256, 256>>>(h0, out + (long)M * Oc);
}

// round 7
// speedup vs baseline: 4.6215x; 1.0948x over previous
#include <cuda_runtime.h>
#include <cuda_bf16.h>
#include <cstdint>
#include <math.h>

#define Bc 64
#define Tc 512
#define Ic 512
#define Hc 512
#define Oc 512

// Scratch
__device__ float    g_z [(long)Bc * Tc * Hc];        // z (fp32)
__device__ float    g_Ph[(long)Bc * Tc * Hc];        // x-part pre-act of h (fp32)
__device__ uint32_t g_x16 [(long)Bc * Tc * Ic / 2];  // x as bf16x2
__device__ uint32_t g_zr16[(long)Bc * Tc * Hc / 2];  // zr (bf16x2)
__device__ uint32_t g_hn16[(long)Bc * Tc * Hc / 2];  // h_new (bf16x2)
__device__ float    g_hpr[Bc * Hc];
__device__ float    g_hpz[Bc * Hc];
__device__ __nv_bfloat16 g_WT16[5l * 512 * 512];     // W^T bf16 [sel][n][k]

__device__ __forceinline__ float sigmoidf_(float x) { return 1.0f / (1.0f + expf(-x)); }

__device__ __forceinline__ uint32_t pk(float lo, float hi) {
    __nv_bfloat162 h = __floats2bfloat162_rn(lo, hi);
    return *reinterpret_cast<uint32_t*>(&h);
}

__device__ __forceinline__ uint32_t smem_u32(const void* p) {
    uint32_t a;
    asm("{ .reg .u64 t; cvta.to.shared.u64 t, %1; cvt.u32.u64 %0, t; }" : "=r"(a) : "l"(p));
    return a;
}

__device__ __forceinline__ void mma_bf16(float* c, const uint32_t* a, const uint32_t* b) {
    asm volatile(
        "mma.sync.aligned.m16n8k16.row.col.f32.bf16.bf16.f32 "
        "{%0,%1,%2,%3}, {%4,%5,%6,%7}, {%8,%9}, {%0,%1,%2,%3};"
        : "+f"(c[0]), "+f"(c[1]), "+f"(c[2]), "+f"(c[3])
        : "r"(a[0]), "r"(a[1]), "r"(a[2]), "r"(a[3]), "r"(b[0]), "r"(b[1]));
}

__device__ __forceinline__ void ldm4(uint32_t* r, uint32_t addr) {
    asm volatile("ldmatrix.sync.aligned.m8n8.x4.shared.b16 {%0,%1,%2,%3}, [%4];"
                 : "=r"(r[0]), "=r"(r[1]), "=r"(r[2]), "=r"(r[3]) : "r"(addr));
}

#define CP16(saddr, gptr) asm volatile("cp.async.cg.shared.global [%0], [%1], 16;" :: "r"(saddr), "l"(gptr))
#define CP_COMMIT()       asm volatile("cp.async.commit_group;" ::: "memory")
#define CP_WAIT1()        asm volatile("cp.async.wait_group 1;" ::: "memory")
#define CP_WAIT0()        asm volatile("cp.async.wait_group 0;" ::: "memory")

// ---------------------------------------------------------------------------
// bf16 mma.sync GEMM, CTA 128 rows, BK=32, cp.async 3-stage, ldmatrix frags.
// SMEM row pitch = 20 u32.
//
// MODE 0: 512 thr, 16 warps (4M x 4N, warp tile 32x16), N-tile 64, 3 accums.
//         A = g_x16 ((b,t) map), B = {Wr_x,Wz_x,Wh_x}^T.
//         Epi: r,z -> zr(bf16), z(f32), Ph(f32).
// MODE 1: 256 thr, 8 warps (4M x 2N), A = g_zr16, B = Wh_h^T, N-tile 128.
//         Epi: h_new -> bf16.
// MODE 2: like MODE 1 with A = g_hn16, B = Wo^T. Epi: sigmoid -> out.
// ---------------------------------------------------------------------------
template <int MODE>
__global__ __launch_bounds__((MODE == 0) ? 512 : 256, (MODE == 0) ? 1 : 2)
void kgemm(float* __restrict__ Cout, const float* __restrict__ bias,
           const float* __restrict__ h0, int Nt, int Tfull)
{
    constexpr int THR   = (MODE == 0) ? 512 : 256;
    constexpr int BROWS = (MODE == 0) ? 192 : 128;
    constexpr int W     = (MODE == 0) ? 3 : 1;
    constexpr int NT    = (MODE == 0) ? 2 : 8;
    constexpr int NTILE = (MODE == 0) ? 64 : 128;
    constexpr int NGRP  = (MODE == 0) ? 3 : 4;       // ldmatrix B x4 groups
    constexpr int ROWS  = 128 + BROWS;
    constexpr int STG   = ROWS * 20;                 // u32 per stage
    constexpr int NCHT  = (ROWS * 4 + THR - 1) / THR;
    constexpr int TOTCH = ROWS * 4;

    extern __shared__ uint32_t sm[];
    const uint32_t sbase = smem_u32(sm);

    const int tid = threadIdx.x;
    const int wid = tid >> 5, lid = tid & 31;
    const int g = lid >> 2, t = lid & 3;
    const int warpM = wid & 3;
    const int warpN = (MODE == 0) ? (wid >> 2) : (wid >> 2);  // 0..3 / 0..1
    constexpr int WNW = (MODE == 0) ? 16 : 64;                // cols per warpN slab
    const int m0 = blockIdx.y * 128;
    const int n0 = blockIdx.x * NTILE;

    const uint32_t* WTu = (const uint32_t*)g_WT16;
    const uint32_t* Ap = (MODE == 0) ? g_x16 : (MODE == 1) ? g_zr16 : g_hn16;
    constexpr int selw = (MODE == 1) ? 3 : 4;

    // ---- cp.async chunk map ----
    const uint32_t* gp[NCHT];
    int soff[NCHT];
    bool cvalid[NCHT];
#pragma unroll
    for (int i = 0; i < NCHT; i++) {
        int c = tid + THR * i;
        cvalid[i] = (c < TOTCH);
        int cc = cvalid[i] ? c : 0;
        if (cc < 512) {
            int row = cc >> 2, q = cc & 3;
            int gm = m0 + row;
            long arow = (MODE == 0) ? ((long)(gm / Nt) * Tfull + (gm % Nt)) : gm;
            gp[i] = Ap + arow * 256 + q * 4;
            soff[i] = row * 20 + q * 4;
        } else {
            int c2 = cc - 512;
            int brow = c2 >> 2, q = c2 & 3;
            long wrow;
            if (MODE == 0) {
                int sel = brow >> 6, nr = brow & 63;
                wrow = (long)sel * 512 + n0 + nr;
            } else {
                wrow = (long)selw * 512 + n0 + brow;
            }
            gp[i] = WTu + wrow * 256 + q * 4;
            soff[i] = (128 + brow) * 20 + q * 4;
        }
    }

    // ---- ldmatrix per-lane base addresses (byte) ----
    const int a_row = warpM * 32 + (lid & 15);
    const int a_kh  = (lid & 16) ? 4 : 0;
    const uint32_t a_addr = sbase + (uint32_t)(a_row * 20 + a_kh) * 4;
    const int b_row = ((lid & 16) ? 8 : 0) + (lid & 7);
    const int b_kh  = (lid & 8) ? 4 : 0;
    const uint32_t b_addr = sbase + (uint32_t)((128 + b_row) * 20 + b_kh) * 4;

    int bgrp_off[NGRP];   // (brow base) * 80 bytes
#pragma unroll
    for (int gb = 0; gb < NGRP; gb++) {
        int base = (MODE == 0) ? (gb * 64 + warpN * 16)
                               : (warpN * 64 + gb * 16);
        bgrp_off[gb] = base * 80;
    }

    float c[W][2][NT][4];
#pragma unroll
    for (int w = 0; w < W; w++)
#pragma unroll
        for (int mt = 0; mt < 2; mt++)
#pragma unroll
            for (int nt = 0; nt < NT; nt++)
#pragma unroll
                for (int q = 0; q < 4; q++) c[w][mt][nt][q] = 0.0f;

    // ---- prologue: stages 0,1 ----
#pragma unroll
    for (int i = 0; i < NCHT; i++) if (cvalid[i]) CP16(sbase + soff[i] * 4, gp[i]);
    CP_COMMIT();
#pragma unroll
    for (int i = 0; i < NCHT; i++) if (cvalid[i]) CP16(sbase + (STG + soff[i]) * 4, gp[i] + 16);
    CP_COMMIT();
    CP_WAIT1();
    __syncthreads();

    // ---- mainloop ----
    for (int kt = 0; kt < 16; kt++) {
        if (kt < 14) {
            const int b2 = ((kt + 2) % 3) * STG;
            const int go = (kt + 2) * 16;
#pragma unroll
            for (int i = 0; i < NCHT; i++) if (cvalid[i]) CP16(sbase + (b2 + soff[i]) * 4, gp[i] + go);
            CP_COMMIT();
        }

        const uint32_t stoff = (uint32_t)((kt % 3) * STG) * 4;
#pragma unroll
        for (int ks = 0; ks < 2; ks++) {
            uint32_t af4[2][4];
#pragma unroll
            for (int mt = 0; mt < 2; mt++)
                ldm4(af4[mt], a_addr + stoff + mt * 1280 + ks * 32);
            uint32_t bf4[NGRP][4];
#pragma unroll
            for (int gb = 0; gb < NGRP; gb++)
                ldm4(bf4[gb], b_addr + stoff + bgrp_off[gb] + ks * 32);

#pragma unroll
            for (int w = 0; w < W; w++)
#pragma unroll
                for (int mt = 0; mt < 2; mt++)
#pragma unroll
                    for (int nt = 0; nt < NT; nt++) {
                        const int gb = (MODE == 0) ? w : (nt >> 1);
                        const int sub = (MODE == 0) ? nt : (nt & 1);
                        mma_bf16(c[w][mt][nt], af4[mt], &bf4[gb][sub * 2]);
                    }
        }

        if (kt < 15) {
            if (kt < 14) CP_WAIT1(); else CP_WAIT0();
            __syncthreads();
        }
    }

    // ---- epilogue ----
#pragma unroll
    for (int mt = 0; mt < 2; mt++) {
#pragma unroll
        for (int rh = 0; rh < 2; rh++) {
            const int m = m0 + warpM * 32 + mt * 16 + g + rh * 8;
            const int b = m / Nt;
#pragma unroll
            for (int nt = 0; nt < NT; nt++) {
                const int n = n0 + warpN * WNW + nt * 8 + t * 2;
                const long idx = (long)m * 512 + n;
                if (MODE == 0) {
                    float vr0 = c[0][mt][nt][rh * 2 + 0], vr1 = c[0][mt][nt][rh * 2 + 1];
                    float vz0 = c[1 % W][mt][nt][rh * 2 + 0], vz1 = c[1 % W][mt][nt][rh * 2 + 1];
                    float vh0 = c[2 % W][mt][nt][rh * 2 + 0], vh1 = c[2 % W][mt][nt][rh * 2 + 1];
                    float r0 = sigmoidf_(vr0 + g_hpr[b * 512 + n]);
                    float r1 = sigmoidf_(vr1 + g_hpr[b * 512 + n + 1]);
                    float z0 = sigmoidf_(vz0 + g_hpz[b * 512 + n]);
                    float z1 = sigmoidf_(vz1 + g_hpz[b * 512 + n + 1]);
                    g_zr16[(long)m * 256 + (n >> 1)] = pk(z0 * r0, z1 * r1);
                    *(float2*)(g_z + idx) = make_float2(z0, z1);
                    *(float2*)(g_Ph + idx) = make_float2(vh0, vh1);
                } else if (MODE == 1) {
                    float v0 = c[0][mt][nt][rh * 2 + 0], v1 = c[0][mt][nt][rh * 2 + 1];
                    float2 zv = *(const float2*)(g_z + idx);
                    float2 pv = *(const float2*)(g_Ph + idx);
                    float2 hv = *(const float2*)(h0 + b * 512 + n);
                    float2 bv = *(const float2*)(bias + n);
                    float o0 = (1.0f - zv.x) * hv.x + zv.x * tanhf(pv.x + v0 + bv.x);
                    float o1 = (1.0f - zv.y) * hv.y + zv.y * tanhf(pv.y + v1 + bv.y);
                    g_hn16[(long)m * 256 + (n >> 1)] = pk(o0, o1);
                } else {
                    float v0 = c[0][mt][nt][rh * 2 + 0], v1 = c[0][mt][nt][rh * 2 + 1];
                    float2 bv = *(const float2*)(bias + n);
                    *(float2*)(Cout + idx) = make_float2(sigmoidf_(v0 + bv.x), sigmoidf_(v1 + bv.y));
                }
            }
        }
    }
}

// ---------------------------------------------------------------------------
__global__ void cvt_x_kernel(const float* __restrict__ src, uint32_t* __restrict__ dst) {
    long i = (long)blockIdx.x * blockDim.x + threadIdx.x;
    float4 v = ((const float4*)src)[i];
    ((uint2*)dst)[i] = make_uint2(pk(v.x, v.y), pk(v.z, v.w));
}

__global__ void transpose_all_bf16(const float* __restrict__ Wr, const float* __restrict__ Wz,
                                   const float* __restrict__ Wh, const float* __restrict__ Wo,
                                   __nv_bfloat16* __restrict__ dst) {
    __shared__ float tbuf[32][33];
    const int sel = blockIdx.z;
    const float* src = (sel == 0) ? Wr : (sel == 1) ? Wz : (sel == 2) ? Wh
                     : (sel == 3) ? (Wh + (long)Ic * Hc) : Wo;
    __nv_bfloat16* d = dst + (long)sel * 512 * 512;
    int bx = blockIdx.x * 32, by = blockIdx.y * 32;
#pragma unroll
    for (int i = 0; i < 4; i++)
        tbuf[threadIdx.y + i * 8][threadIdx.x] = src[(long)(by + threadIdx.y + i * 8) * 512 + bx + threadIdx.x];
    __syncthreads();
#pragma unroll
    for (int i = 0; i < 4; i++)
        d[(long)(bx + threadIdx.y + i * 8) * 512 + by + threadIdx.x] =
            __float2bfloat16(tbuf[threadIdx.x][threadIdx.y + i * 8]);
}

__global__ void hpart_kernel(const float* __restrict__ h0, const float* __restrict__ Wr_h,
                             const float* __restrict__ br, const float* __restrict__ Wz_h,
                             const float* __restrict__ bz) {
    int b = blockIdx.x, n = threadIdx.x;
    float ar = br[n], az = bz[n];
    const float* h0b = h0 + b * Hc;
    for (int k = 0; k < Hc; k++) {
        float h = h0b[k];
        ar = fmaf(h, Wr_h[k * Hc + n], ar);
        az = fmaf(h, Wz_h[k * Hc + n], az);
    }
    g_hpr[b * Hc + n] = ar;
    g_hpz[b * Hc + n] = az;
}

__global__ void copy_h0_kernel(const float* __restrict__ h0, float* __restrict__ dst) {
    int i = blockIdx.x * blockDim.x + threadIdx.x;
    dst[i] = h0[i];
}

// ---------------------------------------------------------------------------
extern "C" void kernel_launch(void* const* d_in, const int* in_sizes, int n_in,
                              void* d_out, int out_size) {
    const float* x  = (const float*)d_in[0];
    const float* h0 = (const float*)d_in[1];
    const float* Wr = (const float*)d_in[2];
    const float* br = (const float*)d_in[3];
    const float* Wz = (const float*)d_in[4];
    const float* bz = (const float*)d_in[5];
    const float* Wh = (const float*)d_in[6];
    const float* bh = (const float*)d_in[7];
    const float* Wo = (const float*)d_in[8];
    const float* bo = (const float*)d_in[9];
    float* out = (float*)d_out;

    long os = out_size;
    int Tfull = in_sizes[0] / (Bc * Ic);
    int Nt;
    bool with_h0;
    if (os > (long)Bc * Hc && ((os - (long)Bc * Hc) % ((long)Bc * Oc)) == 0) {
        Nt = (int)((os - (long)Bc * Hc) / ((long)Bc * Oc));
        with_h0 = true;
    } else {
        Nt = (int)(os / ((long)Bc * Oc));
        with_h0 = false;
    }
    int M = Bc * Nt;

    const int smem0 = 320 * 20 * 3 * 4;
    const int smem12 = 256 * 20 * 3 * 4;
    cudaFuncSetAttribute(kgemm<0>, cudaFuncAttributeMaxDynamicSharedMemorySize, smem0);
    cudaFuncSetAttribute(kgemm<1>, cudaFuncAttributeMaxDynamicSharedMemorySize, smem12);
    cudaFuncSetAttribute(kgemm<2>, cudaFuncAttributeMaxDynamicSharedMemorySize, smem12);

    __nv_bfloat16* wt;
    cudaGetSymbolAddress((void**)&wt, g_WT16);
    uint32_t* x16;
    cudaGetSymbolAddress((void**)&x16, g_x16);

    transpose_all_bf16<<<dim3(16, 16, 5), dim3(32, 8)>>>(Wr, Wz, Wh, Wo, wt);

    long x4 = (long)in_sizes[0] / 4;
    cvt_x_kernel<<<(unsigned)(x4 / 256), 256>>>(x, x16);

    hpart_kernel<<<Bc, Hc>>>(h0, Wr + (long)Ic * Hc, br, Wz + (long)Ic * Hc, bz);

    kgemm<0><<<dim3(8, M / 128), 512, smem0>>>(nullptr, nullptr, nullptr, Nt, Tfull);
    kgemm<1><<<dim3(4, M / 128), 256, smem12>>>(nullptr, bh, h0, Nt, Tfull);
    kgemm<2><<<dim3(4, M / 128), 256, smem12>>>(out, bo, nullptr, Nt, Tfull);

    if (with_h0)
        copy_h0_kernel<<<(Bc * Hc) / 256, 256>>>(h0, out + (long)M * Oc);
}

// round 8
// speedup vs baseline: 5.0097x; 1.0840x over previous
#include <cuda_runtime.h>
#include <cuda_bf16.h>
#include <cstdint>
#include <math.h>

#define Bc 64
#define Tc 512
#define Ic 512
#define Hc 512
#define Oc 512

// Scratch
__device__ uint32_t g_z16 [(long)Bc * Tc * Hc / 2];  // z (bf16x2)
__device__ uint32_t g_Ph16[(long)Bc * Tc * Hc / 2];  // x-part pre-act of h (bf16x2)
__device__ uint32_t g_x16 [(long)Bc * Tc * Ic / 2];  // x as bf16x2
__device__ uint32_t g_zr16[(long)Bc * Tc * Hc / 2];  // zr (bf16x2)
__device__ uint32_t g_hn16[(long)Bc * Tc * Hc / 2];  // h_new (bf16x2)
__device__ float    g_hpr[Bc * Hc];
__device__ float    g_hpz[Bc * Hc];
__device__ __nv_bfloat16 g_WT16[5l * 512 * 512];     // W^T bf16 [sel][n][k]

__device__ __forceinline__ float sigmoidf_(float x) { return 1.0f / (1.0f + expf(-x)); }

__device__ __forceinline__ uint32_t pk(float lo, float hi) {
    __nv_bfloat162 h = __floats2bfloat162_rn(lo, hi);
    return *reinterpret_cast<uint32_t*>(&h);
}
__device__ __forceinline__ float2 upk(uint32_t u) {
    __nv_bfloat162 h = *reinterpret_cast<__nv_bfloat162*>(&u);
    return __bfloat1622float2(h);
}

__device__ __forceinline__ uint32_t smem_u32(const void* p) {
    uint32_t a;
    asm("{ .reg .u64 t; cvta.to.shared.u64 t, %1; cvt.u32.u64 %0, t; }" : "=r"(a) : "l"(p));
    return a;
}

__device__ __forceinline__ void mma_bf16(float* c, const uint32_t* a, const uint32_t* b) {
    asm volatile(
        "mma.sync.aligned.m16n8k16.row.col.f32.bf16.bf16.f32 "
        "{%0,%1,%2,%3}, {%4,%5,%6,%7}, {%8,%9}, {%0,%1,%2,%3};"
        : "+f"(c[0]), "+f"(c[1]), "+f"(c[2]), "+f"(c[3])
        : "r"(a[0]), "r"(a[1]), "r"(a[2]), "r"(a[3]), "r"(b[0]), "r"(b[1]));
}

__device__ __forceinline__ void ldm4(uint32_t* r, uint32_t addr) {
    asm volatile("ldmatrix.sync.aligned.m8n8.x4.shared.b16 {%0,%1,%2,%3}, [%4];"
                 : "=r"(r[0]), "=r"(r[1]), "=r"(r[2]), "=r"(r[3]) : "r"(addr));
}

#define CP16(saddr, gptr) asm volatile("cp.async.cg.shared.global [%0], [%1], 16;" :: "r"(saddr), "l"(gptr))
#define CP_COMMIT()       asm volatile("cp.async.commit_group;" ::: "memory")
#define CP_WAIT1()        asm volatile("cp.async.wait_group 1;" ::: "memory")
#define CP_WAIT0()        asm volatile("cp.async.wait_group 0;" ::: "memory")

// ---------------------------------------------------------------------------
// bf16 mma.sync GEMM, CTA 128 rows, BK=64 (8 chunks), cp.async 3-stage,
// ldmatrix frags. SMEM row pitch = 36 u32 (144B) -> conflict-free ldmatrix.
//
// MODE 0: 512 thr, 16 warps (4M x 4N, warp 32x16), N-tile 64, 3 accums.
//         A = g_x16 ((b,t) map), B = {Wr_x,Wz_x,Wh_x}^T.
//         Epi: r,z -> zr(bf16), z(bf16), Ph(bf16).
// MODE 1: 256 thr, 8 warps (4M x 2N, warp 32x64... warp 32x64 cols), N-tile 128.
//         A = g_zr16, B = Wh_h^T. Epi: h_new -> bf16.
// MODE 2: like MODE 1, A = g_hn16, B = Wo^T. Epi: sigmoid -> out (fp32).
// ---------------------------------------------------------------------------
#define PITCH 36

template <int MODE>
__global__ __launch_bounds__((MODE == 0) ? 512 : 256, (MODE == 0) ? 1 : 2)
void kgemm(float* __restrict__ Cout, const float* __restrict__ bias,
           const float* __restrict__ h0, int Nt, int Tfull)
{
    constexpr int THR   = (MODE == 0) ? 512 : 256;
    constexpr int BROWS = (MODE == 0) ? 192 : 128;
    constexpr int W     = (MODE == 0) ? 3 : 1;
    constexpr int NT    = (MODE == 0) ? 2 : 8;
    constexpr int NTILE = (MODE == 0) ? 64 : 128;
    constexpr int NGRP  = (MODE == 0) ? 3 : 4;
    constexpr int ROWS  = 128 + BROWS;
    constexpr int STG   = ROWS * PITCH;            // u32 per stage
    constexpr int TOTCH = ROWS * 8;                // 16B units per chunk
    constexpr int NCHT  = TOTCH / THR;             // 5 or 8 (exact)

    extern __shared__ uint32_t sm[];
    const uint32_t sbase = smem_u32(sm);

    const int tid = threadIdx.x;
    const int wid = tid >> 5, lid = tid & 31;
    const int g = lid >> 2, t = lid & 3;
    const int warpM = wid & 3;
    const int warpN = wid >> 2;
    constexpr int WNW = (MODE == 0) ? 16 : 64;
    const int m0 = blockIdx.y * 128;
    const int n0 = blockIdx.x * NTILE;

    const uint32_t* WTu = (const uint32_t*)g_WT16;
    const uint32_t* Ap = (MODE == 0) ? g_x16 : (MODE == 1) ? g_zr16 : g_hn16;
    constexpr int selw = (MODE == 1) ? 3 : 4;

    // ---- cp.async chunk map (chunk = 16B, row covers 8 chunks = 64 bf16) ----
    const uint32_t* gp[NCHT];
    int soff[NCHT];
#pragma unroll
    for (int i = 0; i < NCHT; i++) {
        int c = tid + THR * i;
        if (c < 1024) {
            int row = c >> 3, q = c & 7;
            int gm = m0 + row;
            long arow = (MODE == 0) ? ((long)(gm / Nt) * Tfull + (gm % Nt)) : gm;
            gp[i] = Ap + arow * 256 + q * 4;
            soff[i] = row * PITCH + q * 4;
        } else {
            int c2 = c - 1024;
            int brow = c2 >> 3, q = c2 & 7;
            long wrow;
            if (MODE == 0) {
                int sel = brow >> 6, nr = brow & 63;
                wrow = (long)sel * 512 + n0 + nr;
            } else {
                wrow = (long)selw * 512 + n0 + brow;
            }
            gp[i] = WTu + wrow * 256 + q * 4;
            soff[i] = (128 + brow) * PITCH + q * 4;
        }
    }

    // ---- ldmatrix per-lane base addresses (byte); ks stride = 32B ----
    const int a_row = warpM * 32 + (lid & 15);
    const uint32_t a_addr = sbase + (uint32_t)a_row * (PITCH * 4) + ((lid & 16) ? 16 : 0);
    const int b_row = ((lid & 16) ? 8 : 0) + (lid & 7);
    const uint32_t b_addr = sbase + (uint32_t)(128 + b_row) * (PITCH * 4) + ((lid & 8) ? 16 : 0);

    int bgrp_off[NGRP];   // base row * 144 bytes
#pragma unroll
    for (int gb = 0; gb < NGRP; gb++) {
        int base = (MODE == 0) ? (gb * 64 + warpN * 16) : (warpN * 64 + gb * 16);
        bgrp_off[gb] = base * (PITCH * 4);
    }

    float c[W][2][NT][4];
#pragma unroll
    for (int w = 0; w < W; w++)
#pragma unroll
        for (int mt = 0; mt < 2; mt++)
#pragma unroll
            for (int nt = 0; nt < NT; nt++)
#pragma unroll
                for (int q = 0; q < 4; q++) c[w][mt][nt][q] = 0.0f;

    // ---- prologue: stages 0,1 (chunks 0,1) ----
#pragma unroll
    for (int i = 0; i < NCHT; i++) CP16(sbase + soff[i] * 4, gp[i]);
    CP_COMMIT();
#pragma unroll
    for (int i = 0; i < NCHT; i++) CP16(sbase + (STG + soff[i]) * 4, gp[i] + 32);
    CP_COMMIT();
    CP_WAIT1();
    __syncthreads();

    // ---- mainloop: 8 chunks of BK=64 ----
    for (int kt = 0; kt < 8; kt++) {
        if (kt < 6) {
            const int b2 = ((kt + 2) % 3) * STG;
            const int go = (kt + 2) * 32;
#pragma unroll
            for (int i = 0; i < NCHT; i++) CP16(sbase + (b2 + soff[i]) * 4, gp[i] + go);
            CP_COMMIT();
        }

        const uint32_t stoff = (uint32_t)((kt % 3) * STG) * 4;
#pragma unroll
        for (int ks = 0; ks < 4; ks++) {
            uint32_t af4[2][4];
#pragma unroll
            for (int mt = 0; mt < 2; mt++)
                ldm4(af4[mt], a_addr + stoff + mt * (16 * PITCH * 4) + ks * 32);
            uint32_t bf4[NGRP][4];
#pragma unroll
            for (int gb = 0; gb < NGRP; gb++)
                ldm4(bf4[gb], b_addr + stoff + bgrp_off[gb] + ks * 32);

#pragma unroll
            for (int w = 0; w < W; w++)
#pragma unroll
                for (int mt = 0; mt < 2; mt++)
#pragma unroll
                    for (int nt = 0; nt < NT; nt++) {
                        const int gb = (MODE == 0) ? w : (nt >> 1);
                        const int sub = (MODE == 0) ? nt : (nt & 1);
                        mma_bf16(c[w][mt][nt], af4[mt], &bf4[gb][sub * 2]);
                    }
        }

        if (kt < 7) {
            if (kt < 6) CP_WAIT1(); else CP_WAIT0();
            __syncthreads();
        }
    }

    // ---- epilogue ----
#pragma unroll
    for (int mt = 0; mt < 2; mt++) {
#pragma unroll
        for (int rh = 0; rh < 2; rh++) {
            const int m = m0 + warpM * 32 + mt * 16 + g + rh * 8;
            const int b = m / Nt;
#pragma unroll
            for (int nt = 0; nt < NT; nt++) {
                const int n = n0 + warpN * WNW + nt * 8 + t * 2;
                const long hidx = (long)m * 256 + (n >> 1);
                if (MODE == 0) {
                    float vr0 = c[0][mt][nt][rh * 2 + 0], vr1 = c[0][mt][nt][rh * 2 + 1];
                    float vz0 = c[1 % W][mt][nt][rh * 2 + 0], vz1 = c[1 % W][mt][nt][rh * 2 + 1];
                    float vh0 = c[2 % W][mt][nt][rh * 2 + 0], vh1 = c[2 % W][mt][nt][rh * 2 + 1];
                    float r0 = sigmoidf_(vr0 + g_hpr[b * 512 + n]);
                    float r1 = sigmoidf_(vr1 + g_hpr[b * 512 + n + 1]);
                    float z0 = sigmoidf_(vz0 + g_hpz[b * 512 + n]);
                    float z1 = sigmoidf_(vz1 + g_hpz[b * 512 + n + 1]);
                    g_zr16[hidx] = pk(z0 * r0, z1 * r1);
                    g_z16[hidx]  = pk(z0, z1);
                    g_Ph16[hidx] = pk(vh0, vh1);
                } else if (MODE == 1) {
                    float v0 = c[0][mt][nt][rh * 2 + 0], v1 = c[0][mt][nt][rh * 2 + 1];
                    float2 zv = upk(g_z16[hidx]);
                    float2 pv = upk(g_Ph16[hidx]);
                    float2 hv = *(const float2*)(h0 + b * 512 + n);
                    float2 bv = *(const float2*)(bias + n);
                    float o0 = (1.0f - zv.x) * hv.x + zv.x * tanhf(pv.x + v0 + bv.x);
                    float o1 = (1.0f - zv.y) * hv.y + zv.y * tanhf(pv.y + v1 + bv.y);
                    g_hn16[hidx] = pk(o0, o1);
                } else {
                    float v0 = c[0][mt][nt][rh * 2 + 0], v1 = c[0][mt][nt][rh * 2 + 1];
                    float2 bv = *(const float2*)(bias + n);
                    *(float2*)(Cout + (long)m * 512 + n) =
                        make_float2(sigmoidf_(v0 + bv.x), sigmoidf_(v1 + bv.y));
                }
            }
        }
    }
}

// ---------------------------------------------------------------------------
__global__ void cvt_x_kernel(const float* __restrict__ src, uint32_t* __restrict__ dst) {
    long i = (long)blockIdx.x * blockDim.x + threadIdx.x;
    float4 v = ((const float4*)src)[i];
    ((uint2*)dst)[i] = make_uint2(pk(v.x, v.y), pk(v.z, v.w));
}

__global__ void transpose_all_bf16(const float* __restrict__ Wr, const float* __restrict__ Wz,
                                   const float* __restrict__ Wh, const float* __restrict__ Wo,
                                   __nv_bfloat16* __restrict__ dst) {
    __shared__ float tbuf[32][33];
    const int sel = blockIdx.z;
    const float* src = (sel == 0) ? Wr : (sel == 1) ? Wz : (sel == 2) ? Wh
                     : (sel == 3) ? (Wh + (long)Ic * Hc) : Wo;
    __nv_bfloat16* d = dst + (long)sel * 512 * 512;
    int bx = blockIdx.x * 32, by = blockIdx.y * 32;
#pragma unroll
    for (int i = 0; i < 4; i++)
        tbuf[threadIdx.y + i * 8][threadIdx.x] = src[(long)(by + threadIdx.y + i * 8) * 512 + bx + threadIdx.x];
    __syncthreads();
#pragma unroll
    for (int i = 0; i < 4; i++)
        d[(long)(bx + threadIdx.y + i * 8) * 512 + by + threadIdx.x] =
            __float2bfloat16(tbuf[threadIdx.x][threadIdx.y + i * 8]);
}

__global__ void hpart_kernel(const float* __restrict__ h0, const float* __restrict__ Wr_h,
                             const float* __restrict__ br, const float* __restrict__ Wz_h,
                             const float* __restrict__ bz) {
    int b = blockIdx.x, n = threadIdx.x;
    float ar = br[n], az = bz[n];
    const float* h0b = h0 + b * Hc;
    for (int k = 0; k < Hc; k++) {
        float h = h0b[k];
        ar = fmaf(h, Wr_h[k * Hc + n], ar);
        az = fmaf(h, Wz_h[k * Hc + n], az);
    }
    g_hpr[b * Hc + n] = ar;
    g_hpz[b * Hc + n] = az;
}

__global__ void copy_h0_kernel(const float* __restrict__ h0, float* __restrict__ dst) {
    int i = blockIdx.x * blockDim.x + threadIdx.x;
    dst[i] = h0[i];
}

// ---------------------------------------------------------------------------
extern "C" void kernel_launch(void* const* d_in, const int* in_sizes, int n_in,
                              void* d_out, int out_size) {
    const float* x  = (const float*)d_in[0];
    const float* h0 = (const float*)d_in[1];
    const float* Wr = (const float*)d_in[2];
    const float* br = (const float*)d_in[3];
    const float* Wz = (const float*)d_in[4];
    const float* bz = (const float*)d_in[5];
    const float* Wh = (const float*)d_in[6];
    const float* bh = (const float*)d_in[7];
    const float* Wo = (const float*)d_in[8];
    const float* bo = (const float*)d_in[9];
    float* out = (float*)d_out;

    long os = out_size;
    int Tfull = in_sizes[0] / (Bc * Ic);
    int Nt;
    bool with_h0;
    if (os > (long)Bc * Hc && ((os - (long)Bc * Hc) % ((long)Bc * Oc)) == 0) {
        Nt = (int)((os - (long)Bc * Hc) / ((long)Bc * Oc));
        with_h0 = true;
    } else {
        Nt = (int)(os / ((long)Bc * Oc));
        with_h0 = false;
    }
    int M = Bc * Nt;

    const int smem0  = 320 * PITCH * 3 * 4;   // 138240 B
    const int smem12 = 256 * PITCH * 3 * 4;   // 110592 B
    cudaFuncSetAttribute(kgemm<0>, cudaFuncAttributeMaxDynamicSharedMemorySize, smem0);
    cudaFuncSetAttribute(kgemm<1>, cudaFuncAttributeMaxDynamicSharedMemorySize, smem12);
    cudaFuncSetAttribute(kgemm<2>, cudaFuncAttributeMaxDynamicSharedMemorySize, smem12);

    __nv_bfloat16* wt;
    cudaGetSymbolAddress((void**)&wt, g_WT16);
    uint32_t* x16;
    cudaGetSymbolAddress((void**)&x16, g_x16);

    transpose_all_bf16<<<dim3(16, 16, 5), dim3(32, 8)>>>(Wr, Wz, Wh, Wo, wt);

    long x4 = (long)in_sizes[0] / 4;
    cvt_x_kernel<<<(unsigned)(x4 / 256), 256>>>(x, x16);

    hpart_kernel<<<Bc, Hc>>>(h0, Wr + (long)Ic * Hc, br, Wz + (long)Ic * Hc, bz);

    kgemm<0><<<dim3(8, M / 128), 512, smem0>>>(nullptr, nullptr, nullptr, Nt, Tfull);
    kgemm<1><<<dim3(4, M / 128), 256, smem12>>>(nullptr, bh, h0, Nt, Tfull);
    kgemm<2><<<dim3(4, M / 128), 256, smem12>>>(out, bo, nullptr, Nt, Tfull);

    if (with_h0)
        copy_h0_kernel<<<(Bc * Hc) / 256, 256>>>(h0, out + (long)M * Oc);
}

// round 9
// speedup vs baseline: 5.3842x; 1.0747x over previous
#include <cuda_runtime.h>
#include <cuda_bf16.h>
#include <cstdint>
#include <math.h>

#define Bc 64
#define Tc 512
#define Ic 512
#define Hc 512
#define Oc 512

// Scratch
__device__ uint32_t g_z16 [(long)Bc * Tc * Hc / 2];  // z (bf16x2)
__device__ uint32_t g_x16 [(long)Bc * Tc * Ic / 2];  // x as bf16x2
__device__ uint32_t g_zr16[(long)Bc * Tc * Hc / 2];  // zr (bf16x2)
__device__ uint32_t g_hn16[(long)Bc * Tc * Hc / 2];  // h_new (bf16x2)
__device__ float    g_hpr[Bc * Hc];
__device__ float    g_hpz[Bc * Hc];
__device__ __nv_bfloat16 g_WT16[5l * 512 * 512];     // W^T bf16 [sel][n][k]
// slabs: 0=Wr_x 1=Wz_x 2=Wh_x 3=Wh_h 4=Wo

__device__ __forceinline__ float sigmoidf_(float x) { return 1.0f / (1.0f + expf(-x)); }

__device__ __forceinline__ uint32_t pk(float lo, float hi) {
    __nv_bfloat162 h = __floats2bfloat162_rn(lo, hi);
    return *reinterpret_cast<uint32_t*>(&h);
}
__device__ __forceinline__ float2 upk(uint32_t u) {
    __nv_bfloat162 h = *reinterpret_cast<__nv_bfloat162*>(&u);
    return __bfloat1622float2(h);
}

__device__ __forceinline__ uint32_t smem_u32(const void* p) {
    uint32_t a;
    asm("{ .reg .u64 t; cvta.to.shared.u64 t, %1; cvt.u32.u64 %0, t; }" : "=r"(a) : "l"(p));
    return a;
}

__device__ __forceinline__ void mma_bf16(float* c, const uint32_t* a, const uint32_t* b) {
    asm volatile(
        "mma.sync.aligned.m16n8k16.row.col.f32.bf16.bf16.f32 "
        "{%0,%1,%2,%3}, {%4,%5,%6,%7}, {%8,%9}, {%0,%1,%2,%3};"
        : "+f"(c[0]), "+f"(c[1]), "+f"(c[2]), "+f"(c[3])
        : "r"(a[0]), "r"(a[1]), "r"(a[2]), "r"(a[3]), "r"(b[0]), "r"(b[1]));
}

__device__ __forceinline__ void ldm4(uint32_t* r, uint32_t addr) {
    asm volatile("ldmatrix.sync.aligned.m8n8.x4.shared.b16 {%0,%1,%2,%3}, [%4];"
                 : "=r"(r[0]), "=r"(r[1]), "=r"(r[2]), "=r"(r[3]) : "r"(addr));
}

#define CP16(saddr, gptr) asm volatile("cp.async.cg.shared.global [%0], [%1], 16;" :: "r"(saddr), "l"(gptr))
#define CP_COMMIT()       asm volatile("cp.async.commit_group;" ::: "memory")
#define CP_WAIT1()        asm volatile("cp.async.wait_group 1;" ::: "memory")
#define CP_WAIT0()        asm volatile("cp.async.wait_group 0;" ::: "memory")

#define PITCH 36
#define STGB  (256 * PITCH * 4)          // bytes per stage (36864)
#define WSLAB 524288                      // bytes per weight slab in g_WT16

// ---------------------------------------------------------------------------
// bf16 mma.sync GEMM, CTA 128 rows x 128 B-rows, BK=64, cp.async 3-stage,
// ldmatrix frags, pitch 36 u32.
//
// MODE 0: 512 thr, 16 warps (4M x 4N), W=2 accums (Wr_x, Wz_x), N-tile 64.
//         A = x16 ((b,t) map). Frag double-buffer + spread cp.async.
//         Epi: r,z -> zr(bf16), z(bf16).
// MODE 1: 256 thr, 8 warps (4M x 2N), K=1024: A = [zr | x], B = [Wh_h ; Wh_x],
//         N-tile 128. Epi: hn = (1-z)h0 + z*tanh(acc+bh) -> bf16.
// MODE 2: 256 thr, 8 warps, K=512: A = hn, B = Wo. Epi: sigmoid -> out.
// ---------------------------------------------------------------------------
template <int MODE>
__global__ __launch_bounds__((MODE == 0) ? 512 : 256, (MODE == 0) ? 1 : 2)
void kgemm(float* __restrict__ Cout, const float* __restrict__ bias,
           const float* __restrict__ h0, int Nt, int Tfull)
{
    constexpr int THR    = (MODE == 0) ? 512 : 256;
    constexpr int CHUNKS = (MODE == 1) ? 16 : 8;
    constexpr int W      = (MODE == 0) ? 2 : 1;
    constexpr int NT     = (MODE == 0) ? 2 : 8;
    constexpr int NGRP   = (MODE == 0) ? 2 : 4;
    constexpr int NTILE  = (MODE == 0) ? 64 : 128;
    constexpr int WNW    = (MODE == 0) ? 16 : 64;
    constexpr int NCHT   = 2048 / THR;            // 4 (M0) or 8 (M1/2)
    constexpr int AH     = NCHT / 2;              // slots < AH are A-rows

    extern __shared__ uint32_t sm[];
    const uint32_t sbase = smem_u32(sm);

    const int tid = threadIdx.x;
    const int wid = tid >> 5, lid = tid & 31;
    const int g = lid >> 2, t = lid & 3;
    const int warpM = wid & 3;
    const int warpN = wid >> 2;
    const int m0 = blockIdx.y * 128;
    const int n0 = blockIdx.x * NTILE;

    const char* xb  = (const char*)g_x16;
    const char* zrb = (const char*)g_zr16;
    const char* hnb = (const char*)g_hn16;
    const char* wtb = (const char*)g_WT16;

    // ---- per-slot byte offsets ----
    uint32_t offP[NCHT];                 // primary offset (A: zr/x/hn space; B: within-slab or slab0-based)
    uint32_t offX[AH];                   // MODE 1: x-space offsets for k>=512
    uint32_t sofb[NCHT];                 // smem byte offset within stage
#pragma unroll
    for (int i = 0; i < NCHT; i++) {
        int c = tid + THR * i;
        if (i < AH) {
            int row = c >> 3, q = c & 7;
            int gm = m0 + row;
            uint32_t xoff = (uint32_t)((long)(gm / Nt) * Tfull + (gm % Nt)) * 1024u + q * 16;
            if (MODE == 0) offP[i] = xoff;
            else           offP[i] = (uint32_t)gm * 1024u + q * 16;
            if (MODE == 1) offX[i] = xoff;
            sofb[i] = (uint32_t)(row * PITCH + q * 4) * 4;
        } else {
            int c2 = c - 1024;
            int brow = c2 >> 3, q = c2 & 7;
            if (MODE == 0) {
                int sel = brow >> 6, nr = brow & 63;     // 0=Wr_x, 1=Wz_x
                offP[i] = (uint32_t)sel * WSLAB + (uint32_t)(n0 + nr) * 1024u + q * 16;
            } else {
                offP[i] = (uint32_t)(n0 + brow) * 1024u + q * 16;   // slab added per chunk
            }
            sofb[i] = (uint32_t)((128 + brow) * PITCH + q * 4) * 4;
        }
    }

    // ---- ldmatrix per-lane base addresses ----
    const int a_row = warpM * 32 + (lid & 15);
    const uint32_t a_addr = sbase + (uint32_t)a_row * (PITCH * 4) + ((lid & 16) ? 16 : 0);
    const int b_row = ((lid & 16) ? 8 : 0) + (lid & 7);
    const uint32_t b_addr = sbase + (uint32_t)(128 + b_row) * (PITCH * 4) + ((lid & 8) ? 16 : 0);

    uint32_t bgrp_off[NGRP];
#pragma unroll
    for (int gb = 0; gb < NGRP; gb++) {
        int base = (MODE == 0) ? (gb * 64 + warpN * 16) : (warpN * 64 + gb * 16);
        bgrp_off[gb] = (uint32_t)base * (PITCH * 4);
    }

    float c[W][2][NT][4];
#pragma unroll
    for (int w = 0; w < W; w++)
#pragma unroll
        for (int mt = 0; mt < 2; mt++)
#pragma unroll
            for (int nt = 0; nt < NT; nt++)
#pragma unroll
                for (int q = 0; q < 4; q++) c[w][mt][nt][q] = 0.0f;

    // ---- cp.async issue for (slot i, chunk kt) ----
    auto issue = [&](int i, int kt, uint32_t stb) {
        const char* src;
        if (MODE == 0) {
            src = ((i < AH) ? xb : wtb) + offP[i] + kt * 128;
        } else if (MODE == 1) {
            if (i < AH) src = (kt < 8) ? (zrb + offP[i] + kt * 128)
                                       : (xb + offX[i < AH ? i : 0] + (kt - 8) * 128);
            else        src = wtb + offP[i] + ((kt < 8) ? 3u : 2u) * WSLAB + (kt & 7) * 128;
        } else {
            src = ((i < AH) ? (hnb + offP[i]) : (wtb + offP[i] + 4u * WSLAB)) + kt * 128;
        }
        CP16(sbase + stb + sofb[i], src);
    };

    // ---- prologue: chunks 0,1 -> stages 0,1 ----
#pragma unroll
    for (int i = 0; i < NCHT; i++) issue(i, 0, 0);
    CP_COMMIT();
#pragma unroll
    for (int i = 0; i < NCHT; i++) issue(i, 1, STGB);
    CP_COMMIT();
    CP_WAIT1();
    __syncthreads();

    // ---- mainloop ----
    for (int kt = 0; kt < CHUNKS; kt++) {
        const uint32_t stb = (uint32_t)(kt % 3) * STGB;
        const bool pf = (kt < CHUNKS - 2);
        const uint32_t nstb = (uint32_t)((kt + 2) % 3) * STGB;

        if (MODE == 0) {
            // frag double buffer
            uint32_t af[2][2][4], bf[2][2][4];
#pragma unroll
            for (int mt = 0; mt < 2; mt++) ldm4(af[0][mt], a_addr + stb + mt * (16 * PITCH * 4));
#pragma unroll
            for (int gb = 0; gb < 2; gb++) ldm4(bf[0][gb], b_addr + stb + bgrp_off[gb]);
#pragma unroll
            for (int ks = 0; ks < 4; ks++) {
                const int cur = ks & 1, nxt = cur ^ 1;
                if (pf) issue(ks, kt + 2, nstb);          // 1 slot per ks (NCHT=4)
                if (ks < 3) {
#pragma unroll
                    for (int mt = 0; mt < 2; mt++)
                        ldm4(af[nxt][mt], a_addr + stb + mt * (16 * PITCH * 4) + (ks + 1) * 32);
#pragma unroll
                    for (int gb = 0; gb < 2; gb++)
                        ldm4(bf[nxt][gb], b_addr + stb + bgrp_off[gb] + (ks + 1) * 32);
                }
#pragma unroll
                for (int w = 0; w < 2; w++)
#pragma unroll
                    for (int mt = 0; mt < 2; mt++)
#pragma unroll
                        for (int nt = 0; nt < 2; nt++)
                            mma_bf16(c[w][mt][nt], af[cur][mt], &bf[cur][w][nt * 2]);
            }
        } else {
#pragma unroll
            for (int ks = 0; ks < 4; ks++) {
                if (pf) { issue(2 * ks, kt + 2, nstb); issue(2 * ks + 1, kt + 2, nstb); }
                uint32_t af4[2][4];
#pragma unroll
                for (int mt = 0; mt < 2; mt++)
                    ldm4(af4[mt], a_addr + stb + mt * (16 * PITCH * 4) + ks * 32);
                uint32_t bf4[NGRP][4];
#pragma unroll
                for (int gb = 0; gb < NGRP; gb++)
                    ldm4(bf4[gb], b_addr + stb + bgrp_off[gb] + ks * 32);
#pragma unroll
                for (int mt = 0; mt < 2; mt++)
#pragma unroll
                    for (int nt = 0; nt < NT; nt++)
                        mma_bf16(c[0][mt][nt], af4[mt], &bf4[nt >> 1][(nt & 1) * 2]);
            }
        }

        if (pf) CP_COMMIT();
        if (kt < CHUNKS - 1) {
            if (pf) CP_WAIT1(); else CP_WAIT0();
            __syncthreads();
        }
    }

    // ---- epilogue ----
#pragma unroll
    for (int mt = 0; mt < 2; mt++) {
#pragma unroll
        for (int rh = 0; rh < 2; rh++) {
            const int m = m0 + warpM * 32 + mt * 16 + g + rh * 8;
            const int b = m / Nt;
#pragma unroll
            for (int nt = 0; nt < NT; nt++) {
                const int n = n0 + warpN * WNW + nt * 8 + t * 2;
                const long hidx = (long)m * 256 + (n >> 1);
                if (MODE == 0) {
                    float vr0 = c[0][mt][nt][rh * 2 + 0], vr1 = c[0][mt][nt][rh * 2 + 1];
                    float vz0 = c[1 % W][mt][nt][rh * 2 + 0], vz1 = c[1 % W][mt][nt][rh * 2 + 1];
                    float r0 = sigmoidf_(vr0 + g_hpr[b * 512 + n]);
                    float r1 = sigmoidf_(vr1 + g_hpr[b * 512 + n + 1]);
                    float z0 = sigmoidf_(vz0 + g_hpz[b * 512 + n]);
                    float z1 = sigmoidf_(vz1 + g_hpz[b * 512 + n + 1]);
                    g_zr16[hidx] = pk(z0 * r0, z1 * r1);
                    g_z16[hidx]  = pk(z0, z1);
                } else if (MODE == 1) {
                    float v0 = c[0][mt][nt][rh * 2 + 0], v1 = c[0][mt][nt][rh * 2 + 1];
                    float2 zv = upk(g_z16[hidx]);
                    float2 hv = *(const float2*)(h0 + b * 512 + n);
                    float2 bv = *(const float2*)(bias + n);
                    float o0 = (1.0f - zv.x) * hv.x + zv.x * tanhf(v0 + bv.x);
                    float o1 = (1.0f - zv.y) * hv.y + zv.y * tanhf(v1 + bv.y);
                    g_hn16[hidx] = pk(o0, o1);
                } else {
                    float v0 = c[0][mt][nt][rh * 2 + 0], v1 = c[0][mt][nt][rh * 2 + 1];
                    float2 bv = *(const float2*)(bias + n);
                    *(float2*)(Cout + (long)m * 512 + n) =
                        make_float2(sigmoidf_(v0 + bv.x), sigmoidf_(v1 + bv.y));
                }
            }
        }
    }
}

// ---------------------------------------------------------------------------
__global__ void cvt_x_kernel(const float* __restrict__ src, uint32_t* __restrict__ dst) {
    long i = (long)blockIdx.x * blockDim.x + threadIdx.x;
    float4 v = ((const float4*)src)[i];
    ((uint2*)dst)[i] = make_uint2(pk(v.x, v.y), pk(v.z, v.w));
}

__global__ void transpose_all_bf16(const float* __restrict__ Wr, const float* __restrict__ Wz,
                                   const float* __restrict__ Wh, const float* __restrict__ Wo,
                                   __nv_bfloat16* __restrict__ dst) {
    __shared__ float tbuf[32][33];
    const int sel = blockIdx.z;
    const float* src = (sel == 0) ? Wr : (sel == 1) ? Wz : (sel == 2) ? Wh
                     : (sel == 3) ? (Wh + (long)Ic * Hc) : Wo;
    __nv_bfloat16* d = dst + (long)sel * 512 * 512;
    int bx = blockIdx.x * 32, by = blockIdx.y * 32;
#pragma unroll
    for (int i = 0; i < 4; i++)
        tbuf[threadIdx.y + i * 8][threadIdx.x] = src[(long)(by + threadIdx.y + i * 8) * 512 + bx + threadIdx.x];
    __syncthreads();
#pragma unroll
    for (int i = 0; i < 4; i++)
        d[(long)(bx + threadIdx.y + i * 8) * 512 + by + threadIdx.x] =
            __float2bfloat16(tbuf[threadIdx.x][threadIdx.y + i * 8]);
}

__global__ void hpart_kernel(const float* __restrict__ h0, const float* __restrict__ Wr_h,
                             const float* __restrict__ br, const float* __restrict__ Wz_h,
                             const float* __restrict__ bz) {
    int b = blockIdx.x, n = threadIdx.x;
    float ar = br[n], az = bz[n];
    const float* h0b = h0 + b * Hc;
    for (int k = 0; k < Hc; k++) {
        float h = h0b[k];
        ar = fmaf(h, Wr_h[k * Hc + n], ar);
        az = fmaf(h, Wz_h[k * Hc + n], az);
    }
    g_hpr[b * Hc + n] = ar;
    g_hpz[b * Hc + n] = az;
}

__global__ void copy_h0_kernel(const float* __restrict__ h0, float* __restrict__ dst) {
    int i = blockIdx.x * blockDim.x + threadIdx.x;
    dst[i] = h0[i];
}

// ---------------------------------------------------------------------------
extern "C" void kernel_launch(void* const* d_in, const int* in_sizes, int n_in,
                              void* d_out, int out_size) {
    const float* x  = (const float*)d_in[0];
    const float* h0 = (const float*)d_in[1];
    const float* Wr = (const float*)d_in[2];
    const float* br = (const float*)d_in[3];
    const float* Wz = (const float*)d_in[4];
    const float* bz = (const float*)d_in[5];
    const float* Wh = (const float*)d_in[6];
    const float* bh = (const float*)d_in[7];
    const float* Wo = (const float*)d_in[8];
    const float* bo = (const float*)d_in[9];
    float* out = (float*)d_out;

    long os = out_size;
    int Tfull = in_sizes[0] / (Bc * Ic);
    int Nt;
    bool with_h0;
    if (os > (long)Bc * Hc && ((os - (long)Bc * Hc) % ((long)Bc * Oc)) == 0) {
        Nt = (int)((os - (long)Bc * Hc) / ((long)Bc * Oc));
        with_h0 = true;
    } else {
        Nt = (int)(os / ((long)Bc * Oc));
        with_h0 = false;
    }
    int M = Bc * Nt;

    const int smemB = 3 * STGB;   // 110592 for all modes
    cudaFuncSetAttribute(kgemm<0>, cudaFuncAttributeMaxDynamicSharedMemorySize, smemB);
    cudaFuncSetAttribute(kgemm<1>, cudaFuncAttributeMaxDynamicSharedMemorySize, smemB);
    cudaFuncSetAttribute(kgemm<2>, cudaFuncAttributeMaxDynamicSharedMemorySize, smemB);

    __nv_bfloat16* wt;
    cudaGetSymbolAddress((void**)&wt, g_WT16);
    uint32_t* x16;
    cudaGetSymbolAddress((void**)&x16, g_x16);

    transpose_all_bf16<<<dim3(16, 16, 5), dim3(32, 8)>>>(Wr, Wz, Wh, Wo, wt);

    long x4 = (long)in_sizes[0] / 4;
    cvt_x_kernel<<<(unsigned)(x4 / 256), 256>>>(x, x16);

    hpart_kernel<<<Bc, Hc>>>(h0, Wr + (long)Ic * Hc, br, Wz + (long)Ic * Hc, bz);

    // Stage 1: r,z gates (Wr_x, Wz_x fused)
    kgemm<0><<<dim3(8, M / 128), 512, smemB>>>(nullptr, nullptr, nullptr, Nt, Tfull);
    // Stage 2: hn via K=1024 GEMM [zr|x] @ [Wh_h ; Wh_x]
    kgemm<1><<<dim3(4, M / 128), 256, smemB>>>(nullptr, bh, h0, Nt, Tfull);
    // Stage 3: out
    kgemm<2><<<dim3(4, M / 128), 256, smemB>>>(out, bo, nullptr, Nt, Tfull);

    if (with_h0)
        copy_h0_kernel<<<(Bc * Hc) / 256, 256>>>(h0, out + (long)M * Oc);
}